// round 1
// baseline (speedup 1.0000x reference)
#include <cuda_runtime.h>
#include <cstdint>

#define DINLINE __device__ __forceinline__

// ---------------------------------------------------------------------------
// tf32 helpers
// ---------------------------------------------------------------------------
DINLINE uint32_t f2tf(float x) {
    uint32_t r;
    asm("cvt.rna.tf32.f32 %0, %1;" : "=r"(r) : "f"(x));
    return r;
}

DINLINE void mma8(float c[4], const uint32_t a[4], const uint32_t b[2]) {
    asm volatile(
        "mma.sync.aligned.m16n8k8.row.col.f32.tf32.tf32.f32 "
        "{%0,%1,%2,%3}, {%4,%5,%6,%7}, {%8,%9}, {%0,%1,%2,%3};"
        : "+f"(c[0]), "+f"(c[1]), "+f"(c[2]), "+f"(c[3])
        : "r"(a[0]), "r"(a[1]), "r"(a[2]), "r"(a[3]), "r"(b[0]), "r"(b[1]));
}

// ---------------------------------------------------------------------------
// Scratch (device globals; no dynamic allocation allowed)
// ---------------------------------------------------------------------------
__device__ float g_Q[1048576];
__device__ float g_K[1048576];
__device__ float g_V[1048576];
__device__ float g_Vt[1048576];
__device__ float g_G[1048576];
__device__ float g_O[1048576];
__device__ float g_Z[16777216];   // [h][i][j]
__device__ float g_S[16777216];   // [h][i][j], becomes P in-place after softmax
__device__ float g_WzT[2048];     // [h][c]

// ---------------------------------------------------------------------------
// Generic NT GEMM on tf32 tensor cores.
//   C[m,n] = epi( alpha * sum_k A[m,k] * B[n,k] )
// A row-major [M, lda-stride], B row-major [N, ldb-stride] (K contiguous both).
// C addressed as C[m*ldcm + n*ldcn]  (supports transposed output for Z).
// Batched via blockIdx.z with per-operand strides.
// BK fixed 32. 256 threads. Warps laid out (BM/WM) x (BN/WN), must be 8.
// ---------------------------------------------------------------------------
template <int BM, int BN, int WM, int WN, bool HAS_BIAS, int ACT, bool MASKED>
__global__ __launch_bounds__(256) void gemm_nt(
    const float* __restrict__ A, long sAb, int lda,
    const float* __restrict__ B, long sBb, int ldb,
    float* __restrict__ C, long sCb, long ldcm, long ldcn,
    const float* __restrict__ bias, const float* __restrict__ mask,
    int K, float alpha)
{
    constexpr int BK = 32;
    constexpr int LDSS = 36;                 // 32 + 4 pad (144B rows, 16B aligned)
    constexpr int WARPS_N = BN / WN;
    constexpr int MT = WM / 16;
    constexpr int NT = WN / 8;

    __shared__ uint32_t As[BM * LDSS];
    __shared__ uint32_t Bs[BN * LDSS];

    const int tid = threadIdx.x;
    const int w = tid >> 5, lane = tid & 31;
    const int g = lane >> 2, t = lane & 3;
    const int wn = w % WARPS_N, wm = w / WARPS_N;
    const long bm0 = (long)blockIdx.x * BM;
    const int bn0 = blockIdx.y * BN;

    A += (long)blockIdx.z * sAb;
    B += (long)blockIdx.z * sBb;
    C += (long)blockIdx.z * sCb;

    float acc[MT][NT][4];
#pragma unroll
    for (int mt = 0; mt < MT; mt++)
#pragma unroll
        for (int nt = 0; nt < NT; nt++)
#pragma unroll
            for (int e = 0; e < 4; e++) acc[mt][nt][e] = 0.f;

    for (int k0 = 0; k0 < K; k0 += BK) {
        __syncthreads();
        // stage A tile (convert to tf32 at store)
#pragma unroll
        for (int idx = tid; idx < BM * 8; idx += 256) {
            int r = idx >> 3, c = (idx & 7) << 2;
            const float4 v = *reinterpret_cast<const float4*>(A + (bm0 + r) * lda + k0 + c);
            uint4 u = make_uint4(f2tf(v.x), f2tf(v.y), f2tf(v.z), f2tf(v.w));
            *reinterpret_cast<uint4*>(&As[r * LDSS + c]) = u;
        }
        // stage B tile
#pragma unroll
        for (int idx = tid; idx < BN * 8; idx += 256) {
            int r = idx >> 3, c = (idx & 7) << 2;
            const float4 v = *reinterpret_cast<const float4*>(B + (long)(bn0 + r) * ldb + k0 + c);
            uint4 u = make_uint4(f2tf(v.x), f2tf(v.y), f2tf(v.z), f2tf(v.w));
            *reinterpret_cast<uint4*>(&Bs[r * LDSS + c]) = u;
        }
        __syncthreads();

#pragma unroll
        for (int ks = 0; ks < 4; ks++) {
            uint32_t af[MT][4];
#pragma unroll
            for (int mt = 0; mt < MT; mt++) {
                int m = wm * WM + mt * 16;
                af[mt][0] = As[(m + g) * LDSS + ks * 8 + t];
                af[mt][1] = As[(m + g + 8) * LDSS + ks * 8 + t];
                af[mt][2] = As[(m + g) * LDSS + ks * 8 + t + 4];
                af[mt][3] = As[(m + g + 8) * LDSS + ks * 8 + t + 4];
            }
#pragma unroll
            for (int nt = 0; nt < NT; nt++) {
                int n = wn * WN + nt * 8;
                uint32_t bf[2];
                bf[0] = Bs[(n + g) * LDSS + ks * 8 + t];
                bf[1] = Bs[(n + g) * LDSS + ks * 8 + t + 4];
#pragma unroll
                for (int mt = 0; mt < MT; mt++) mma8(acc[mt][nt], af[mt], bf);
            }
        }
    }

    // epilogue
#pragma unroll
    for (int mt = 0; mt < MT; mt++) {
#pragma unroll
        for (int nt = 0; nt < NT; nt++) {
#pragma unroll
            for (int e = 0; e < 4; e++) {
                long m = bm0 + wm * WM + mt * 16 + g + ((e >> 1) ? 8 : 0);
                int n = bn0 + wn * WN + nt * 8 + 2 * t + (e & 1);
                float v = acc[mt][nt][e] * alpha;
                if (HAS_BIAS) v += bias[n];
                if (ACT == 1) v = 1.f / (1.f + expf(-v));
                if (MASKED) v += (1.f - mask[m & 1023]) * -1000000.f;
                C[m * ldcm + (long)n * ldcn] = v;
            }
        }
    }
}

// ---------------------------------------------------------------------------
// Row softmax over 1024 columns, in place: S <- softmax(S + Z) row-wise.
// One block per row (16*1024 rows), 256 threads, 4 elems/thread in registers.
// ---------------------------------------------------------------------------
__global__ __launch_bounds__(256) void softmax_k(float* __restrict__ S,
                                                 const float* __restrict__ Z)
{
    const long base = (long)blockIdx.x * 1024;
    const int tid = threadIdx.x;
    float4 s = *reinterpret_cast<float4*>(S + base + tid * 4);
    const float4 z = *reinterpret_cast<const float4*>(Z + base + tid * 4);
    float v0 = s.x + z.x, v1 = s.y + z.y, v2 = s.z + z.z, v3 = s.w + z.w;

    __shared__ float red[8];
    float m = fmaxf(fmaxf(v0, v1), fmaxf(v2, v3));
#pragma unroll
    for (int o = 16; o; o >>= 1) m = fmaxf(m, __shfl_xor_sync(0xFFFFFFFFu, m, o));
    if ((tid & 31) == 0) red[tid >> 5] = m;
    __syncthreads();
    float bm = red[0];
#pragma unroll
    for (int i = 1; i < 8; i++) bm = fmaxf(bm, red[i]);
    __syncthreads();

    v0 = expf(v0 - bm); v1 = expf(v1 - bm); v2 = expf(v2 - bm); v3 = expf(v3 - bm);
    float sum = v0 + v1 + v2 + v3;
#pragma unroll
    for (int o = 16; o; o >>= 1) sum += __shfl_xor_sync(0xFFFFFFFFu, sum, o);
    if ((tid & 31) == 0) red[tid >> 5] = sum;
    __syncthreads();
    float tot = 0.f;
#pragma unroll
    for (int i = 0; i < 8; i++) tot += red[i];
    const float inv = 1.f / tot;

    float4 out = make_float4(v0 * inv, v1 * inv, v2 * inv, v3 * inv);
    *reinterpret_cast<float4*>(S + base + tid * 4) = out;
}

// ---------------------------------------------------------------------------
// 1024x1024 transpose: out[x][y] = in[y][x]
// ---------------------------------------------------------------------------
__global__ void transpose_k(const float* __restrict__ in, float* __restrict__ out)
{
    __shared__ float tile[32][33];
    const int bx = blockIdx.x * 32, by = blockIdx.y * 32;
#pragma unroll
    for (int i = 0; i < 32; i += 8)
        tile[threadIdx.y + i][threadIdx.x] =
            in[(long)(by + threadIdx.y + i) * 1024 + bx + threadIdx.x];
    __syncthreads();
#pragma unroll
    for (int i = 0; i < 32; i += 8)
        out[(long)(bx + threadIdx.y + i) * 1024 + by + threadIdx.x] =
            tile[threadIdx.x][threadIdx.y + i];
}

__global__ void wzt_k(const float* __restrict__ Wz, float* __restrict__ WzT)
{
    for (int idx = threadIdx.x; idx < 2048; idx += 256) {
        int c = idx >> 4, h = idx & 15;
        WzT[h * 128 + c] = Wz[c * 16 + h];
    }
}

__global__ void gate_k(float* __restrict__ O, const float* __restrict__ G)
{
    int i = blockIdx.x * blockDim.x + threadIdx.x;
    float4 o = reinterpret_cast<float4*>(O)[i];
    const float4 g = reinterpret_cast<const float4*>(G)[i];
    o.x *= g.x; o.y *= g.y; o.z *= g.z; o.w *= g.w;
    reinterpret_cast<float4*>(O)[i] = o;
}

// ---------------------------------------------------------------------------
// Launch
// ---------------------------------------------------------------------------
extern "C" void kernel_launch(void* const* d_in, const int* in_sizes, int n_in,
                              void* d_out, int out_size)
{
    const float* s    = (const float*)d_in[0];
    const float* k_in = (const float*)d_in[1];
    const float* mask = (const float*)d_in[2];
    const float* bias = (const float*)d_in[3];
    const float* Wq   = (const float*)d_in[4];
    const float* bq   = (const float*)d_in[5];
    const float* Wk   = (const float*)d_in[6];
    const float* Wv   = (const float*)d_in[7];
    const float* Wg   = (const float*)d_in[8];
    const float* Wo   = (const float*)d_in[9];
    const float* Wz   = (const float*)d_in[10];
    float* out = (float*)d_out;

    float *Q, *Kp, *V, *Vt, *G, *O, *Z, *S, *WzT;
    cudaGetSymbolAddress((void**)&Q,   g_Q);
    cudaGetSymbolAddress((void**)&Kp,  g_K);
    cudaGetSymbolAddress((void**)&V,   g_V);
    cudaGetSymbolAddress((void**)&Vt,  g_Vt);
    cudaGetSymbolAddress((void**)&G,   g_G);
    cudaGetSymbolAddress((void**)&O,   g_O);
    cudaGetSymbolAddress((void**)&Z,   g_Z);
    cudaGetSymbolAddress((void**)&S,   g_S);
    cudaGetSymbolAddress((void**)&WzT, g_WzT);

    const dim3 blk(256);

    // Projections: Q = s@Wq^T + bq ; K = k@Wk^T ; V = k@Wv^T ; G = sigmoid(s@Wg^T)
    gemm_nt<128,128,32,64,true, 0,false><<<dim3(8,8,1), blk>>>(
        s, 0, 1024, Wq, 0, 1024, Q, 0, 1024, 1, bq, nullptr, 1024, 1.f);
    gemm_nt<128,128,32,64,false,0,false><<<dim3(8,8,1), blk>>>(
        k_in, 0, 1024, Wk, 0, 1024, Kp, 0, 1024, 1, nullptr, nullptr, 1024, 1.f);
    gemm_nt<128,128,32,64,false,0,false><<<dim3(8,8,1), blk>>>(
        k_in, 0, 1024, Wv, 0, 1024, V, 0, 1024, 1, nullptr, nullptr, 1024, 1.f);
    gemm_nt<128,128,32,64,false,1,false><<<dim3(8,8,1), blk>>>(
        s, 0, 1024, Wg, 0, 1024, G, 0, 1024, 1, nullptr, nullptr, 1024, 1.f);

    // Z[h,i,j] = bias[i,j,:] @ Wz[:,h] + (1-mask[j]) * (-1e6)
    wzt_k<<<1, 256>>>(Wz, WzT);
    gemm_nt<128,16,32,8,false,0,true><<<dim3(8192,1,1), blk>>>(
        bias, 0, 128, WzT, 0, 128, Z, 0, 1, 1048576, nullptr, mask, 128, 1.f);

    // S[h,i,j] = (Q_h @ K_h^T) / 8   (batched over heads)
    gemm_nt<128,128,32,64,false,0,false><<<dim3(8,8,16), blk>>>(
        Q, 64, 1024, Kp, 64, 1024, S, 1048576, 1024, 1, nullptr, nullptr, 64, 0.125f);

    // P = softmax(S + Z), in place over S
    softmax_k<<<16384, 256>>>(S, Z);

    // O[i, h*64+d] = P_h @ V_h  (via V transposed to [h][d][j])
    transpose_k<<<dim3(32,32), dim3(32,8)>>>(V, Vt);
    gemm_nt<128,64,32,32,false,0,false><<<dim3(8,1,16), blk>>>(
        S, 1048576, 1024, Vt, 65536, 1024, O, 64, 1024, 1, nullptr, nullptr, 1024, 1.f);

    // out = (G * O) @ Wo^T
    gate_k<<<1024, 256>>>(O, G);
    gemm_nt<128,128,32,64,false,0,false><<<dim3(8,8,1), blk>>>(
        O, 0, 1024, Wo, 0, 1024, out, 0, 1024, 1, nullptr, nullptr, 1024, 1.f);
}

// round 2
// speedup vs baseline: 1.6871x; 1.6871x over previous
#include <cuda_runtime.h>
#include <cstdint>

#define DINLINE __device__ __forceinline__

// ---------------------------------------------------------------------------
// helpers
// ---------------------------------------------------------------------------
DINLINE uint32_t f2tf(float x) {
    uint32_t r;
    asm("cvt.rna.tf32.f32 %0, %1;" : "=r"(r) : "f"(x));
    return r;
}

DINLINE void mma8(float c[4], const uint32_t a[4], const uint32_t b[2]) {
    asm volatile(
        "mma.sync.aligned.m16n8k8.row.col.f32.tf32.tf32.f32 "
        "{%0,%1,%2,%3}, {%4,%5,%6,%7}, {%8,%9}, {%0,%1,%2,%3};"
        : "+f"(c[0]), "+f"(c[1]), "+f"(c[2]), "+f"(c[3])
        : "r"(a[0]), "r"(a[1]), "r"(a[2]), "r"(a[3]), "r"(b[0]), "r"(b[1]));
}

DINLINE void cpa16(void* sm, const void* g) {
    uint32_t a = (uint32_t)__cvta_generic_to_shared(sm);
    asm volatile("cp.async.cg.shared.global [%0], [%1], 16;\n" :: "r"(a), "l"(g));
}
DINLINE void cpa_commit() { asm volatile("cp.async.commit_group;\n"); }
template <int N> DINLINE void cpa_wait() { asm volatile("cp.async.wait_group %0;\n" :: "n"(N)); }

// ---------------------------------------------------------------------------
// Scratch
// ---------------------------------------------------------------------------
__device__ float g_Q[1048576];
__device__ float g_K[1048576];
__device__ float g_Vt[1048576];   // [h][d][j]
__device__ float g_G[1048576];
__device__ float g_O[1048576];
__device__ float g_Z[16777216];   // [h][i][j]
__device__ float g_S[16777216];   // [h][i][j] -> P in place
__device__ float g_WzT[2048];     // [h][c]

// ---------------------------------------------------------------------------
// Pipelined tf32 GEMM core: acc += A[BMxK] * B[BNxK]^T   (NT layout, K contig)
// 3-stage cp.async pipeline, raw f32 in smem, cvt->tf32 at fragment load.
// 256 threads. LDS row stride 36 floats (conflict-free, 16B aligned).
// ---------------------------------------------------------------------------
template <int BM, int BN, int WM, int WN>
DINLINE void core_mma(const float* __restrict__ Ab, int lda,
                      const float* __restrict__ Bb, int ldb, int K,
                      float* sA, float* sB,
                      float (&acc)[WM / 16][WN / 8][4])
{
    constexpr int LDS = 36, BK = 32, S = 3;
    constexpr int WNC = BN / WN;
    constexpr int MT = WM / 16, NT = WN / 8;
    const int tid = threadIdx.x, lane = tid & 31, w = tid >> 5;
    const int g = lane >> 2, t4 = lane & 3;
    const int wn = w % WNC, wm = w / WNC;

    auto load_stage = [&](int tt, int st) {
        const float* Ak = Ab + tt * BK;
        const float* Bk = Bb + tt * BK;
        float* dA = sA + st * BM * LDS;
        float* dB = sB + st * BN * LDS;
#pragma unroll
        for (int idx = tid; idx < BM * 8; idx += 256) {
            int r = idx >> 3, c = (idx & 7) << 2;
            cpa16(dA + r * LDS + c, Ak + (long)r * lda + c);
        }
#pragma unroll
        for (int idx = tid; idx < BN * 8; idx += 256) {
            int r = idx >> 3, c = (idx & 7) << 2;
            cpa16(dB + r * LDS + c, Bk + (long)r * ldb + c);
        }
    };

    const int T = K / BK;
#pragma unroll
    for (int tt = 0; tt < S - 1; tt++) {
        if (tt < T) load_stage(tt, tt);
        cpa_commit();
    }

    for (int tt = 0; tt < T; tt++) {
        cpa_wait<S - 2>();
        __syncthreads();
        int tn = tt + S - 1;
        if (tn < T) load_stage(tn, tn % S);
        cpa_commit();

        const float* cA = sA + (tt % S) * BM * LDS;
        const float* cB = sB + (tt % S) * BN * LDS;
#pragma unroll
        for (int ks = 0; ks < 4; ks++) {
            uint32_t af[MT][4], bf[NT][2];
#pragma unroll
            for (int mt = 0; mt < MT; mt++) {
                int m = wm * WM + mt * 16;
                af[mt][0] = f2tf(cA[(m + g) * LDS + ks * 8 + t4]);
                af[mt][1] = f2tf(cA[(m + g + 8) * LDS + ks * 8 + t4]);
                af[mt][2] = f2tf(cA[(m + g) * LDS + ks * 8 + t4 + 4]);
                af[mt][3] = f2tf(cA[(m + g + 8) * LDS + ks * 8 + t4 + 4]);
            }
#pragma unroll
            for (int nt = 0; nt < NT; nt++) {
                int n = wn * WN + nt * 8;
                bf[nt][0] = f2tf(cB[(n + g) * LDS + ks * 8 + t4]);
                bf[nt][1] = f2tf(cB[(n + g) * LDS + ks * 8 + t4 + 4]);
            }
#pragma unroll
            for (int mt = 0; mt < MT; mt++)
#pragma unroll
                for (int nt = 0; nt < NT; nt++) mma8(acc[mt][nt], af[mt], bf[nt]);
        }
    }
}

// ---------------------------------------------------------------------------
// Generic pipelined GEMM kernel (batched, flexible C addressing, opt. mask)
// ---------------------------------------------------------------------------
template <int BM, int BN, int WM, int WN, bool MASKED>
__global__ __launch_bounds__(256) void tgemm(
    const float* __restrict__ A, long sAb, int lda,
    const float* __restrict__ B, long sBb, int ldb,
    float* __restrict__ C, long sCb, long ldcm, long ldcn,
    const float* __restrict__ mask, int K, float alpha)
{
    extern __shared__ float sm[];
    float* sA = sm;
    float* sB = sm + 3 * BM * 36;
    constexpr int MT = WM / 16, NT = WN / 8, WNC = BN / WN;

    const long bm0 = (long)blockIdx.x * BM, bn0 = (long)blockIdx.y * BN;
    const float* Ab = A + (long)blockIdx.z * sAb + bm0 * lda;
    const float* Bb = B + (long)blockIdx.z * sBb + bn0 * ldb;
    float* Cb = C + (long)blockIdx.z * sCb;

    float acc[MT][NT][4];
#pragma unroll
    for (int mt = 0; mt < MT; mt++)
#pragma unroll
        for (int nt = 0; nt < NT; nt++)
#pragma unroll
            for (int e = 0; e < 4; e++) acc[mt][nt][e] = 0.f;

    core_mma<BM, BN, WM, WN>(Ab, lda, Bb, ldb, K, sA, sB, acc);

    const int tid = threadIdx.x, lane = tid & 31, w = tid >> 5;
    const int g = lane >> 2, t4 = lane & 3;
    const int wn = w % WNC, wm = w / WNC;
#pragma unroll
    for (int mt = 0; mt < MT; mt++)
#pragma unroll
        for (int nt = 0; nt < NT; nt++)
#pragma unroll
            for (int e = 0; e < 4; e++) {
                long m = bm0 + wm * WM + mt * 16 + g + ((e >> 1) ? 8 : 0);
                long n = bn0 + wn * WN + nt * 8 + 2 * t4 + (e & 1);
                float v = acc[mt][nt][e] * alpha;
                if (MASKED) v += (1.f - mask[m & 1023]) * -1000000.f;
                Cb[m * ldcm + n * ldcn] = v;
            }
}

// ---------------------------------------------------------------------------
// Fused 4-projection GEMM: z=0 Q(+bias), z=1 K, z=2 V (written transposed),
// z=3 G (sigmoid). 128x128 tiles, grid (8,8,4).
// ---------------------------------------------------------------------------
__global__ __launch_bounds__(256) void proj4_k(
    const float* __restrict__ s, const float* __restrict__ kin,
    const float* __restrict__ Wq, const float* __restrict__ bq,
    const float* __restrict__ Wk, const float* __restrict__ Wv,
    const float* __restrict__ Wg,
    float* __restrict__ Q, float* __restrict__ Kp,
    float* __restrict__ Vt, float* __restrict__ G)
{
    extern __shared__ float sm[];
    float* sA = sm;
    float* sB = sm + 3 * 128 * 36;
    const int z = blockIdx.z;
    const float* A = (z == 0 || z == 3) ? s : kin;
    const float* B = (z == 0) ? Wq : (z == 1) ? Wk : (z == 2) ? Wv : Wg;

    const long bm0 = (long)blockIdx.x * 128, bn0 = (long)blockIdx.y * 128;
    float acc[2][8][4];
#pragma unroll
    for (int mt = 0; mt < 2; mt++)
#pragma unroll
        for (int nt = 0; nt < 8; nt++)
#pragma unroll
            for (int e = 0; e < 4; e++) acc[mt][nt][e] = 0.f;

    core_mma<128, 128, 32, 64>(A + bm0 * 1024, 1024, B + bn0 * 1024, 1024, 1024,
                               sA, sB, acc);

    const int tid = threadIdx.x, lane = tid & 31, w = tid >> 5;
    const int g = lane >> 2, t4 = lane & 3;
    const int wn = w & 1, wm = w >> 1;
#pragma unroll
    for (int mt = 0; mt < 2; mt++)
#pragma unroll
        for (int nt = 0; nt < 8; nt++)
#pragma unroll
            for (int e = 0; e < 4; e++) {
                long m = bm0 + wm * 32 + mt * 16 + g + ((e >> 1) ? 8 : 0);
                long n = bn0 + wn * 64 + nt * 8 + 2 * t4 + (e & 1);
                float v = acc[mt][nt][e];
                if (z == 0)      Q[m * 1024 + n] = v + bq[n];
                else if (z == 1) Kp[m * 1024 + n] = v;
                else if (z == 2) Vt[n * 1024 + m] = v;      // [h][d][j]
                else             G[m * 1024 + n] = 1.f / (1.f + expf(-v));
            }
}

// ---------------------------------------------------------------------------
// Row softmax over 1024 cols, in place: S <- softmax(S + Z)
// ---------------------------------------------------------------------------
__global__ __launch_bounds__(256) void softmax_k(float* __restrict__ S,
                                                 const float* __restrict__ Z)
{
    const long base = (long)blockIdx.x * 1024;
    const int tid = threadIdx.x;
    float4 sv = *reinterpret_cast<float4*>(S + base + tid * 4);
    const float4 z = *reinterpret_cast<const float4*>(Z + base + tid * 4);
    float v0 = sv.x + z.x, v1 = sv.y + z.y, v2 = sv.z + z.z, v3 = sv.w + z.w;

    __shared__ float red[8];
    float m = fmaxf(fmaxf(v0, v1), fmaxf(v2, v3));
#pragma unroll
    for (int o = 16; o; o >>= 1) m = fmaxf(m, __shfl_xor_sync(0xFFFFFFFFu, m, o));
    if ((tid & 31) == 0) red[tid >> 5] = m;
    __syncthreads();
    float bm = red[0];
#pragma unroll
    for (int i = 1; i < 8; i++) bm = fmaxf(bm, red[i]);
    __syncthreads();

    v0 = expf(v0 - bm); v1 = expf(v1 - bm); v2 = expf(v2 - bm); v3 = expf(v3 - bm);
    float sum = v0 + v1 + v2 + v3;
#pragma unroll
    for (int o = 16; o; o >>= 1) sum += __shfl_xor_sync(0xFFFFFFFFu, sum, o);
    if ((tid & 31) == 0) red[tid >> 5] = sum;
    __syncthreads();
    float tot = 0.f;
#pragma unroll
    for (int i = 0; i < 8; i++) tot += red[i];
    const float inv = 1.f / tot;

    *reinterpret_cast<float4*>(S + base + tid * 4) =
        make_float4(v0 * inv, v1 * inv, v2 * inv, v3 * inv);
}

__global__ void wzt_k(const float* __restrict__ Wz, float* __restrict__ WzT)
{
    for (int idx = threadIdx.x; idx < 2048; idx += 256) {
        int c = idx >> 4, h = idx & 15;
        WzT[h * 128 + c] = Wz[c * 16 + h];
    }
}

__global__ void gate_k(float* __restrict__ O, const float* __restrict__ G)
{
    int i = blockIdx.x * blockDim.x + threadIdx.x;
    float4 o = reinterpret_cast<float4*>(O)[i];
    const float4 g = reinterpret_cast<const float4*>(G)[i];
    o.x *= g.x; o.y *= g.y; o.z *= g.z; o.w *= g.w;
    reinterpret_cast<float4*>(O)[i] = o;
}

// ---------------------------------------------------------------------------
// Launch
// ---------------------------------------------------------------------------
extern "C" void kernel_launch(void* const* d_in, const int* in_sizes, int n_in,
                              void* d_out, int out_size)
{
    const float* s    = (const float*)d_in[0];
    const float* k_in = (const float*)d_in[1];
    const float* mask = (const float*)d_in[2];
    const float* bias = (const float*)d_in[3];
    const float* Wq   = (const float*)d_in[4];
    const float* bq   = (const float*)d_in[5];
    const float* Wk   = (const float*)d_in[6];
    const float* Wv   = (const float*)d_in[7];
    const float* Wg   = (const float*)d_in[8];
    const float* Wo   = (const float*)d_in[9];
    const float* Wz   = (const float*)d_in[10];
    float* out = (float*)d_out;

    float *Q, *Kp, *Vt, *G, *O, *Z, *S, *WzT;
    cudaGetSymbolAddress((void**)&Q,   g_Q);
    cudaGetSymbolAddress((void**)&Kp,  g_K);
    cudaGetSymbolAddress((void**)&Vt,  g_Vt);
    cudaGetSymbolAddress((void**)&G,   g_G);
    cudaGetSymbolAddress((void**)&O,   g_O);
    cudaGetSymbolAddress((void**)&Z,   g_Z);
    cudaGetSymbolAddress((void**)&S,   g_S);
    cudaGetSymbolAddress((void**)&WzT, g_WzT);

    // dynamic smem sizes (3 stages, LDS=36 floats)
    const int SM_PROJ  = 3 * (128 + 128) * 36 * 4;  // 110592
    const int SM_Z     = 3 * (128 + 16)  * 36 * 4;  //  62208
    const int SM_6464  = 3 * (64 + 64)   * 36 * 4;  //  55296
    const int SM_64128 = 3 * (64 + 128)  * 36 * 4;  //  82944

    cudaFuncSetAttribute((const void*)proj4_k,
                         cudaFuncAttributeMaxDynamicSharedMemorySize, SM_PROJ);
    cudaFuncSetAttribute((const void*)tgemm<128, 16, 32, 8, true>,
                         cudaFuncAttributeMaxDynamicSharedMemorySize, SM_Z);
    cudaFuncSetAttribute((const void*)tgemm<64, 64, 16, 32, false>,
                         cudaFuncAttributeMaxDynamicSharedMemorySize, SM_6464);
    cudaFuncSetAttribute((const void*)tgemm<64, 128, 16, 64, false>,
                         cudaFuncAttributeMaxDynamicSharedMemorySize, SM_64128);

    const dim3 blk(256);

    // Q,K,V(t),G projections fused (fills the chip)
    proj4_k<<<dim3(8, 8, 4), blk, SM_PROJ>>>(s, k_in, Wq, bq, Wk, Wv, Wg,
                                             Q, Kp, Vt, G);

    // Z[h,i,j] = bias[i,j,:] @ Wz[:,h]  + mask
    wzt_k<<<1, 256>>>(Wz, WzT);
    tgemm<128, 16, 32, 8, true><<<dim3(8192, 1, 1), blk, SM_Z>>>(
        bias, 0, 128, WzT, 0, 128, Z, 0, 1, 1048576, mask, 128, 1.f);

    // S[h,i,j] = (Q_h @ K_h^T) / 8
    tgemm<64, 64, 16, 32, false><<<dim3(16, 16, 16), blk, SM_6464>>>(
        Q, 64, 1024, Kp, 64, 1024, S, 1048576, 1024, 1, nullptr, 64, 0.125f);

    // P = softmax(S + Z) in place
    softmax_k<<<16384, 256>>>(S, Z);

    // O[i, h*64+d] = P_h @ V_h   (B = Vt[h][d][j])
    tgemm<64, 64, 16, 32, false><<<dim3(16, 1, 16), blk, SM_6464>>>(
        S, 1048576, 1024, Vt, 65536, 1024, O, 64, 1024, 1, nullptr, 1024, 1.f);

    // out = (G*O) @ Wo^T
    gate_k<<<1024, 256>>>(O, G);
    tgemm<64, 128, 16, 64, false><<<dim3(16, 8, 1), blk, SM_64128>>>(
        O, 0, 1024, Wo, 0, 1024, out, 0, 1024, 1, nullptr, 1024, 1.f);
}

// round 3
// speedup vs baseline: 1.9337x; 1.1462x over previous
#include <cuda_runtime.h>
#include <cstdint>

#define DINLINE __device__ __forceinline__

// ---------------------------------------------------------------------------
// helpers
// ---------------------------------------------------------------------------
DINLINE uint32_t f2tf(float x) {
    uint32_t r;
    asm("cvt.rna.tf32.f32 %0, %1;" : "=r"(r) : "f"(x));
    return r;
}

DINLINE void mma8(float c[4], const uint32_t a[4], const uint32_t b[2]) {
    asm volatile(
        "mma.sync.aligned.m16n8k8.row.col.f32.tf32.tf32.f32 "
        "{%0,%1,%2,%3}, {%4,%5,%6,%7}, {%8,%9}, {%0,%1,%2,%3};"
        : "+f"(c[0]), "+f"(c[1]), "+f"(c[2]), "+f"(c[3])
        : "r"(a[0]), "r"(a[1]), "r"(a[2]), "r"(a[3]), "r"(b[0]), "r"(b[1]));
}

DINLINE void cpa16(void* sm, const void* g) {
    uint32_t a = (uint32_t)__cvta_generic_to_shared(sm);
    asm volatile("cp.async.cg.shared.global [%0], [%1], 16;\n" :: "r"(a), "l"(g));
}
DINLINE void cpa_commit() { asm volatile("cp.async.commit_group;\n"); }
template <int N> DINLINE void cpa_wait() { asm volatile("cp.async.wait_group %0;\n" :: "n"(N)); }

// ---------------------------------------------------------------------------
// Scratch
// ---------------------------------------------------------------------------
__device__ float g_Q[1048576];
__device__ float g_K[1048576];
__device__ float g_Vt[1048576];   // [h][d][j]
__device__ float g_G[1048576];
__device__ float g_O[1048576];
__device__ float g_Z[16777216];   // [h][i][j]
__device__ float g_WzT[2048];     // [h][c]

// ---------------------------------------------------------------------------
// Pipelined tf32 GEMM core (NT: both operands K-contiguous)
// ---------------------------------------------------------------------------
template <int BM, int BN, int WM, int WN>
DINLINE void core_mma(const float* __restrict__ Ab, int lda,
                      const float* __restrict__ Bb, int ldb, int K,
                      float* sA, float* sB,
                      float (&acc)[WM / 16][WN / 8][4])
{
    constexpr int LDS = 36, BK = 32, S = 3;
    constexpr int WNC = BN / WN;
    constexpr int MT = WM / 16, NT = WN / 8;
    const int tid = threadIdx.x, lane = tid & 31, w = tid >> 5;
    const int g = lane >> 2, t4 = lane & 3;
    const int wn = w % WNC, wm = w / WNC;

    auto load_stage = [&](int tt, int st) {
        const float* Ak = Ab + tt * BK;
        const float* Bk = Bb + tt * BK;
        float* dA = sA + st * BM * LDS;
        float* dB = sB + st * BN * LDS;
#pragma unroll
        for (int idx = tid; idx < BM * 8; idx += 256) {
            int r = idx >> 3, c = (idx & 7) << 2;
            cpa16(dA + r * LDS + c, Ak + (long)r * lda + c);
        }
#pragma unroll
        for (int idx = tid; idx < BN * 8; idx += 256) {
            int r = idx >> 3, c = (idx & 7) << 2;
            cpa16(dB + r * LDS + c, Bk + (long)r * ldb + c);
        }
    };

    const int T = K / BK;
#pragma unroll
    for (int tt = 0; tt < S - 1; tt++) {
        if (tt < T) load_stage(tt, tt);
        cpa_commit();
    }

    for (int tt = 0; tt < T; tt++) {
        cpa_wait<S - 2>();
        __syncthreads();
        int tn = tt + S - 1;
        if (tn < T) load_stage(tn, tn % S);
        cpa_commit();

        const float* cA = sA + (tt % S) * BM * LDS;
        const float* cB = sB + (tt % S) * BN * LDS;
#pragma unroll
        for (int ks = 0; ks < 4; ks++) {
            uint32_t af[MT][4], bf[NT][2];
#pragma unroll
            for (int mt = 0; mt < MT; mt++) {
                int m = wm * WM + mt * 16;
                af[mt][0] = f2tf(cA[(m + g) * LDS + ks * 8 + t4]);
                af[mt][1] = f2tf(cA[(m + g + 8) * LDS + ks * 8 + t4]);
                af[mt][2] = f2tf(cA[(m + g) * LDS + ks * 8 + t4 + 4]);
                af[mt][3] = f2tf(cA[(m + g + 8) * LDS + ks * 8 + t4 + 4]);
            }
#pragma unroll
            for (int nt = 0; nt < NT; nt++) {
                int n = wn * WN + nt * 8;
                bf[nt][0] = f2tf(cB[(n + g) * LDS + ks * 8 + t4]);
                bf[nt][1] = f2tf(cB[(n + g) * LDS + ks * 8 + t4 + 4]);
            }
#pragma unroll
            for (int mt = 0; mt < MT; mt++)
#pragma unroll
                for (int nt = 0; nt < NT; nt++) mma8(acc[mt][nt], af[mt], bf[nt]);
        }
    }
}

// ---------------------------------------------------------------------------
// Generic pipelined GEMM (batched, flexible C addressing, optional mask)
// ---------------------------------------------------------------------------
template <int BM, int BN, int WM, int WN, bool MASKED>
__global__ __launch_bounds__(256) void tgemm(
    const float* __restrict__ A, long sAb, int lda,
    const float* __restrict__ B, long sBb, int ldb,
    float* __restrict__ C, long sCb, long ldcm, long ldcn,
    const float* __restrict__ mask, int K, float alpha)
{
    extern __shared__ float sm[];
    float* sA = sm;
    float* sB = sm + 3 * BM * 36;
    constexpr int MT = WM / 16, NT = WN / 8, WNC = BN / WN;

    const long bm0 = (long)blockIdx.x * BM, bn0 = (long)blockIdx.y * BN;
    const float* Ab = A + (long)blockIdx.z * sAb + bm0 * lda;
    const float* Bb = B + (long)blockIdx.z * sBb + bn0 * ldb;
    float* Cb = C + (long)blockIdx.z * sCb;

    float acc[MT][NT][4];
#pragma unroll
    for (int mt = 0; mt < MT; mt++)
#pragma unroll
        for (int nt = 0; nt < NT; nt++)
#pragma unroll
            for (int e = 0; e < 4; e++) acc[mt][nt][e] = 0.f;

    core_mma<BM, BN, WM, WN>(Ab, lda, Bb, ldb, K, sA, sB, acc);

    const int tid = threadIdx.x, lane = tid & 31, w = tid >> 5;
    const int g = lane >> 2, t4 = lane & 3;
    const int wn = w % WNC, wm = w / WNC;
#pragma unroll
    for (int mt = 0; mt < MT; mt++)
#pragma unroll
        for (int nt = 0; nt < NT; nt++)
#pragma unroll
            for (int e = 0; e < 4; e++) {
                long m = bm0 + wm * WM + mt * 16 + g + ((e >> 1) ? 8 : 0);
                long n = bn0 + wn * WN + nt * 8 + 2 * t4 + (e & 1);
                float v = acc[mt][nt][e] * alpha;
                if (MASKED) v += (1.f - mask[m & 1023]) * -1000000.f;
                Cb[m * ldcm + n * ldcn] = v;
            }
}

// ---------------------------------------------------------------------------
// Fused 4-projection GEMM: z=0 Q(+bias), z=1 K, z=2 V (transposed), z=3 G (sig)
// ---------------------------------------------------------------------------
__global__ __launch_bounds__(256) void proj4_k(
    const float* __restrict__ s, const float* __restrict__ kin,
    const float* __restrict__ Wq, const float* __restrict__ bq,
    const float* __restrict__ Wk, const float* __restrict__ Wv,
    const float* __restrict__ Wg,
    float* __restrict__ Q, float* __restrict__ Kp,
    float* __restrict__ Vt, float* __restrict__ G)
{
    extern __shared__ float sm[];
    float* sA = sm;
    float* sB = sm + 3 * 128 * 36;
    const int z = blockIdx.z;
    const float* A = (z == 0 || z == 3) ? s : kin;
    const float* B = (z == 0) ? Wq : (z == 1) ? Wk : (z == 2) ? Wv : Wg;

    const long bm0 = (long)blockIdx.x * 128, bn0 = (long)blockIdx.y * 128;
    float acc[2][8][4];
#pragma unroll
    for (int mt = 0; mt < 2; mt++)
#pragma unroll
        for (int nt = 0; nt < 8; nt++)
#pragma unroll
            for (int e = 0; e < 4; e++) acc[mt][nt][e] = 0.f;

    core_mma<128, 128, 32, 64>(A + bm0 * 1024, 1024, B + bn0 * 1024, 1024, 1024,
                               sA, sB, acc);

    const int tid = threadIdx.x, lane = tid & 31, w = tid >> 5;
    const int g = lane >> 2, t4 = lane & 3;
    const int wn = w & 1, wm = w >> 1;
#pragma unroll
    for (int mt = 0; mt < 2; mt++)
#pragma unroll
        for (int nt = 0; nt < 8; nt++)
#pragma unroll
            for (int e = 0; e < 4; e++) {
                long m = bm0 + wm * 32 + mt * 16 + g + ((e >> 1) ? 8 : 0);
                long n = bn0 + wn * 64 + nt * 8 + 2 * t4 + (e & 1);
                float v = acc[mt][nt][e];
                if (z == 0)      Q[m * 1024 + n] = v + bq[n];
                else if (z == 1) Kp[m * 1024 + n] = v;
                else if (z == 2) Vt[n * 1024 + m] = v;      // [h][d][j]
                else             G[m * 1024 + n] = 1.f / (1.f + expf(-v));
            }
}

// ---------------------------------------------------------------------------
// Flash attention per (i-tile 64, head): S=QK^T/8+Z -> online softmax -> P@V,
// gated by G at the epilogue. 128 threads = 4 warps x (16 rows, full 64 cols).
// Smem: 6 tiles [64][68] f32: K0,K1,V0,V1,Z0,Z1 (P overlays current K buf).
// ---------------------------------------------------------------------------
#define FT 4352                     // 64*68 floats per tile
__global__ __launch_bounds__(128) void flash_k(
    const float* __restrict__ Q, const float* __restrict__ K,
    const float* __restrict__ Vt, const float* __restrict__ Z,
    const float* __restrict__ G, float* __restrict__ O)
{
    extern __shared__ float sm[];
    const int h = blockIdx.y;
    const long i0 = (long)blockIdx.x * 64;
    const int tid = threadIdx.x, w = tid >> 5, lane = tid & 31;
    const int g = lane >> 2, t4 = lane & 3;
    const int r0 = w * 16 + g;                // local row; pair row r0+8

    // persistent Q fragments: rows (i0+r0, i0+r0+8), cols h*64 + [0,64)
    uint32_t qa[8][4];
    {
        const float* Qb = Q + (i0) * 1024 + h * 64;
#pragma unroll
        for (int ks = 0; ks < 8; ks++) {
            qa[ks][0] = f2tf(Qb[(long)r0 * 1024 + ks * 8 + t4]);
            qa[ks][1] = f2tf(Qb[(long)(r0 + 8) * 1024 + ks * 8 + t4]);
            qa[ks][2] = f2tf(Qb[(long)r0 * 1024 + ks * 8 + t4 + 4]);
            qa[ks][3] = f2tf(Qb[(long)(r0 + 8) * 1024 + ks * 8 + t4 + 4]);
        }
    }

    float oacc[8][4];
#pragma unroll
    for (int nt = 0; nt < 8; nt++)
#pragma unroll
        for (int e = 0; e < 4; e++) oacc[nt][e] = 0.f;
    float m0 = -1e30f, m1 = -1e30f, l0 = 0.f, l1 = 0.f;

    auto stage = [&](int jt, int b) {
        const float* Ksrc = K + (long)jt * 64 * 1024 + h * 64;
        const float* Vsrc = Vt + (long)h * 65536 + jt * 64;
        const float* Zsrc = Z + (long)h * 1048576 + i0 * 1024 + jt * 64;
        float* dK = sm + b * FT;
        float* dV = sm + (2 + b) * FT;
        float* dZ = sm + (4 + b) * FT;
#pragma unroll
        for (int idx = tid; idx < 1024; idx += 128) {
            int r = idx >> 4, c = (idx & 15) << 2;
            cpa16(dK + r * 68 + c, Ksrc + (long)r * 1024 + c);
            cpa16(dV + r * 68 + c, Vsrc + (long)r * 1024 + c);
            cpa16(dZ + r * 68 + c, Zsrc + (long)r * 1024 + c);
        }
    };

    stage(0, 0);
    cpa_commit();

    for (int jt = 0; jt < 16; jt++) {
        const int b = jt & 1;
        cpa_wait<0>();
        __syncthreads();
        if (jt < 15) { stage(jt + 1, b ^ 1); cpa_commit(); }

        const float* cK = sm + b * FT;
        const float* cV = sm + (2 + b) * FT;
        const float* cZ = sm + (4 + b) * FT;

        // S = Q K^T  (N = j 64, K-dim = d 64)
        float sacc[8][4];
#pragma unroll
        for (int nt = 0; nt < 8; nt++)
#pragma unroll
            for (int e = 0; e < 4; e++) sacc[nt][e] = 0.f;
#pragma unroll
        for (int ks = 0; ks < 8; ks++) {
#pragma unroll
            for (int nt = 0; nt < 8; nt++) {
                uint32_t bf[2];
                bf[0] = f2tf(cK[(nt * 8 + g) * 68 + ks * 8 + t4]);
                bf[1] = f2tf(cK[(nt * 8 + g) * 68 + ks * 8 + t4 + 4]);
                mma8(sacc[nt], qa[ks], bf);
            }
        }

        // scale + Z
#pragma unroll
        for (int nt = 0; nt < 8; nt++) {
            const float2 z0 = *reinterpret_cast<const float2*>(
                &cZ[r0 * 68 + nt * 8 + 2 * t4]);
            const float2 z1 = *reinterpret_cast<const float2*>(
                &cZ[(r0 + 8) * 68 + nt * 8 + 2 * t4]);
            sacc[nt][0] = fmaf(sacc[nt][0], 0.125f, z0.x);
            sacc[nt][1] = fmaf(sacc[nt][1], 0.125f, z0.y);
            sacc[nt][2] = fmaf(sacc[nt][2], 0.125f, z1.x);
            sacc[nt][3] = fmaf(sacc[nt][3], 0.125f, z1.y);
        }

        // row maxima (quad reduction over t4)
        float mx0 = -1e30f, mx1 = -1e30f;
#pragma unroll
        for (int nt = 0; nt < 8; nt++) {
            mx0 = fmaxf(mx0, fmaxf(sacc[nt][0], sacc[nt][1]));
            mx1 = fmaxf(mx1, fmaxf(sacc[nt][2], sacc[nt][3]));
        }
        mx0 = fmaxf(mx0, __shfl_xor_sync(0xFFFFFFFFu, mx0, 1));
        mx0 = fmaxf(mx0, __shfl_xor_sync(0xFFFFFFFFu, mx0, 2));
        mx1 = fmaxf(mx1, __shfl_xor_sync(0xFFFFFFFFu, mx1, 1));
        mx1 = fmaxf(mx1, __shfl_xor_sync(0xFFFFFFFFu, mx1, 2));

        const float mn0 = fmaxf(m0, mx0), mn1 = fmaxf(m1, mx1);
        const float a0 = __expf(m0 - mn0), a1 = __expf(m1 - mn1);
        m0 = mn0; m1 = mn1;

        float rs0 = 0.f, rs1 = 0.f;
#pragma unroll
        for (int nt = 0; nt < 8; nt++) {
            sacc[nt][0] = __expf(sacc[nt][0] - mn0);
            sacc[nt][1] = __expf(sacc[nt][1] - mn0);
            sacc[nt][2] = __expf(sacc[nt][2] - mn1);
            sacc[nt][3] = __expf(sacc[nt][3] - mn1);
            rs0 += sacc[nt][0] + sacc[nt][1];
            rs1 += sacc[nt][2] + sacc[nt][3];
        }
        rs0 += __shfl_xor_sync(0xFFFFFFFFu, rs0, 1);
        rs0 += __shfl_xor_sync(0xFFFFFFFFu, rs0, 2);
        rs1 += __shfl_xor_sync(0xFFFFFFFFu, rs1, 1);
        rs1 += __shfl_xor_sync(0xFFFFFFFFu, rs1, 2);
        l0 = l0 * a0 + rs0;
        l1 = l1 * a1 + rs1;
#pragma unroll
        for (int nt = 0; nt < 8; nt++) {
            oacc[nt][0] *= a0; oacc[nt][1] *= a0;
            oacc[nt][2] *= a1; oacc[nt][3] *= a1;
        }

        // P overlays current K buffer (all warps finished reading K)
        __syncthreads();
        uint32_t* pP = (uint32_t*)(sm + b * FT);
#pragma unroll
        for (int nt = 0; nt < 8; nt++) {
            uint2 p0 = make_uint2(f2tf(sacc[nt][0]), f2tf(sacc[nt][1]));
            uint2 p1 = make_uint2(f2tf(sacc[nt][2]), f2tf(sacc[nt][3]));
            *reinterpret_cast<uint2*>(&pP[r0 * 68 + nt * 8 + 2 * t4]) = p0;
            *reinterpret_cast<uint2*>(&pP[(r0 + 8) * 68 + nt * 8 + 2 * t4]) = p1;
        }
        __syncwarp();

        // O += P @ V   (A = P rows i, k = j; B = Vt rows d, k = j)
#pragma unroll
        for (int ks = 0; ks < 8; ks++) {
            uint32_t pa[4];
            pa[0] = pP[r0 * 68 + ks * 8 + t4];
            pa[1] = pP[(r0 + 8) * 68 + ks * 8 + t4];
            pa[2] = pP[r0 * 68 + ks * 8 + t4 + 4];
            pa[3] = pP[(r0 + 8) * 68 + ks * 8 + t4 + 4];
#pragma unroll
            for (int nt = 0; nt < 8; nt++) {
                uint32_t bf[2];
                bf[0] = f2tf(cV[(nt * 8 + g) * 68 + ks * 8 + t4]);
                bf[1] = f2tf(cV[(nt * 8 + g) * 68 + ks * 8 + t4 + 4]);
                mma8(oacc[nt], pa, bf);
            }
        }
    }

    // epilogue: o/l * G, write O[i, h*64+d]
    const float iv0 = 1.f / l0, iv1 = 1.f / l1;
#pragma unroll
    for (int nt = 0; nt < 8; nt++) {
        const int c = h * 64 + nt * 8 + 2 * t4;
        const long ro0 = (i0 + r0) * 1024 + c;
        const long ro1 = (i0 + r0 + 8) * 1024 + c;
        const float2 g0 = *reinterpret_cast<const float2*>(&G[ro0]);
        const float2 g1 = *reinterpret_cast<const float2*>(&G[ro1]);
        float2 o0 = make_float2(oacc[nt][0] * iv0 * g0.x, oacc[nt][1] * iv0 * g0.y);
        float2 o1 = make_float2(oacc[nt][2] * iv1 * g1.x, oacc[nt][3] * iv1 * g1.y);
        *reinterpret_cast<float2*>(&O[ro0]) = o0;
        *reinterpret_cast<float2*>(&O[ro1]) = o1;
    }
}

__global__ void wzt_k(const float* __restrict__ Wz, float* __restrict__ WzT)
{
    for (int idx = threadIdx.x; idx < 2048; idx += 256) {
        int c = idx >> 4, h = idx & 15;
        WzT[h * 128 + c] = Wz[c * 16 + h];
    }
}

// ---------------------------------------------------------------------------
// Launch
// ---------------------------------------------------------------------------
extern "C" void kernel_launch(void* const* d_in, const int* in_sizes, int n_in,
                              void* d_out, int out_size)
{
    const float* s    = (const float*)d_in[0];
    const float* k_in = (const float*)d_in[1];
    const float* mask = (const float*)d_in[2];
    const float* bias = (const float*)d_in[3];
    const float* Wq   = (const float*)d_in[4];
    const float* bq   = (const float*)d_in[5];
    const float* Wk   = (const float*)d_in[6];
    const float* Wv   = (const float*)d_in[7];
    const float* Wg   = (const float*)d_in[8];
    const float* Wo   = (const float*)d_in[9];
    const float* Wz   = (const float*)d_in[10];
    float* out = (float*)d_out;

    float *Q, *Kp, *Vt, *G, *O, *Z, *WzT;
    cudaGetSymbolAddress((void**)&Q,   g_Q);
    cudaGetSymbolAddress((void**)&Kp,  g_K);
    cudaGetSymbolAddress((void**)&Vt,  g_Vt);
    cudaGetSymbolAddress((void**)&G,   g_G);
    cudaGetSymbolAddress((void**)&O,   g_O);
    cudaGetSymbolAddress((void**)&Z,   g_Z);
    cudaGetSymbolAddress((void**)&WzT, g_WzT);

    const int SM_PROJ  = 3 * (128 + 128) * 36 * 4;  // 110592
    const int SM_Z     = 3 * (128 + 16)  * 36 * 4;  //  62208
    const int SM_64128 = 3 * (64 + 128)  * 36 * 4;  //  82944
    const int SM_FLASH = 6 * FT * 4;                // 104448

    cudaFuncSetAttribute((const void*)proj4_k,
                         cudaFuncAttributeMaxDynamicSharedMemorySize, SM_PROJ);
    cudaFuncSetAttribute((const void*)tgemm<128, 16, 32, 8, true>,
                         cudaFuncAttributeMaxDynamicSharedMemorySize, SM_Z);
    cudaFuncSetAttribute((const void*)tgemm<64, 128, 16, 64, false>,
                         cudaFuncAttributeMaxDynamicSharedMemorySize, SM_64128);
    cudaFuncSetAttribute((const void*)flash_k,
                         cudaFuncAttributeMaxDynamicSharedMemorySize, SM_FLASH);

    const dim3 blk(256);

    // Q,K,V(t),G projections fused
    proj4_k<<<dim3(8, 8, 4), blk, SM_PROJ>>>(s, k_in, Wq, bq, Wk, Wv, Wg,
                                             Q, Kp, Vt, G);

    // Z[h,i,j] = bias[i,j,:] @ Wz[:,h]  + mask
    wzt_k<<<1, 256>>>(Wz, WzT);
    tgemm<128, 16, 32, 8, true><<<dim3(8192, 1, 1), blk, SM_Z>>>(
        bias, 0, 128, WzT, 0, 128, Z, 0, 1, 1048576, mask, 128, 1.f);

    // fused attention: softmax(QK^T/8 + Z) @ V, gated by G -> O
    flash_k<<<dim3(16, 16), dim3(128), SM_FLASH>>>(Q, Kp, Vt, Z, G, O);

    // out = O_gated @ Wo^T
    tgemm<64, 128, 16, 64, false><<<dim3(16, 8, 1), blk, SM_64128>>>(
        O, 0, 1024, Wo, 0, 1024, out, 0, 1024, 1, nullptr, 1024, 1.f);
}

// round 4
// speedup vs baseline: 2.0465x; 1.0583x over previous
#include <cuda_runtime.h>
#include <cuda_bf16.h>
#include <cstdint>

#define DINLINE __device__ __forceinline__

// ---------------------------------------------------------------------------
// helpers
// ---------------------------------------------------------------------------
DINLINE uint32_t f2tf(float x) {
    uint32_t r;
    asm("cvt.rna.tf32.f32 %0, %1;" : "=r"(r) : "f"(x));
    return r;
}

DINLINE void mma8(float c[4], const uint32_t a[4], const uint32_t b[2]) {
    asm volatile(
        "mma.sync.aligned.m16n8k8.row.col.f32.tf32.tf32.f32 "
        "{%0,%1,%2,%3}, {%4,%5,%6,%7}, {%8,%9}, {%0,%1,%2,%3};"
        : "+f"(c[0]), "+f"(c[1]), "+f"(c[2]), "+f"(c[3])
        : "r"(a[0]), "r"(a[1]), "r"(a[2]), "r"(a[3]), "r"(b[0]), "r"(b[1]));
}

DINLINE void cpa16(void* sm, const void* g) {
    uint32_t a = (uint32_t)__cvta_generic_to_shared(sm);
    asm volatile("cp.async.cg.shared.global [%0], [%1], 16;\n" :: "r"(a), "l"(g));
}
DINLINE void cpa_commit() { asm volatile("cp.async.commit_group;\n"); }
template <int N> DINLINE void cpa_wait() { asm volatile("cp.async.wait_group %0;\n" :: "n"(N)); }

// ---------------------------------------------------------------------------
// Scratch
// ---------------------------------------------------------------------------
__device__ float g_Q[1048576];     // tf32-rounded bits
__device__ float g_K[1048576];     // tf32-rounded bits
__device__ float g_Vt[1048576];    // [h][d][j], tf32-rounded bits
__device__ float g_G[1048576];
__device__ float g_O[1048576];
__device__ __nv_bfloat16 g_Z[16777216];  // [h][i][j] bf16
__device__ float g_WzT[2048];      // [h][c]

// ---------------------------------------------------------------------------
// Pipelined tf32 GEMM core (NT: both operands K-contiguous)
// ---------------------------------------------------------------------------
template <int BM, int BN, int WM, int WN, int TPB>
DINLINE void core_mma(const float* __restrict__ Ab, int lda,
                      const float* __restrict__ Bb, int ldb, int K,
                      float* sA, float* sB,
                      float (&acc)[WM / 16][WN / 8][4])
{
    constexpr int LDS = 36, BK = 32, S = 3;
    constexpr int WNC = BN / WN;
    constexpr int MT = WM / 16, NT = WN / 8;
    const int tid = threadIdx.x, lane = tid & 31, w = tid >> 5;
    const int g = lane >> 2, t4 = lane & 3;
    const int wn = w % WNC, wm = w / WNC;

    auto load_stage = [&](int tt, int st) {
        const float* Ak = Ab + tt * BK;
        const float* Bk = Bb + tt * BK;
        float* dA = sA + st * BM * LDS;
        float* dB = sB + st * BN * LDS;
#pragma unroll
        for (int idx = tid; idx < BM * 8; idx += TPB) {
            int r = idx >> 3, c = (idx & 7) << 2;
            cpa16(dA + r * LDS + c, Ak + (long)r * lda + c);
        }
#pragma unroll
        for (int idx = tid; idx < BN * 8; idx += TPB) {
            int r = idx >> 3, c = (idx & 7) << 2;
            cpa16(dB + r * LDS + c, Bk + (long)r * ldb + c);
        }
    };

    const int T = K / BK;
#pragma unroll
    for (int tt = 0; tt < S - 1; tt++) {
        if (tt < T) load_stage(tt, tt);
        cpa_commit();
    }

    for (int tt = 0; tt < T; tt++) {
        cpa_wait<S - 2>();
        __syncthreads();
        int tn = tt + S - 1;
        if (tn < T) load_stage(tn, tn % S);
        cpa_commit();

        const float* cA = sA + (tt % S) * BM * LDS;
        const float* cB = sB + (tt % S) * BN * LDS;
#pragma unroll
        for (int ks = 0; ks < 4; ks++) {
            uint32_t af[MT][4], bf[NT][2];
#pragma unroll
            for (int mt = 0; mt < MT; mt++) {
                int m = wm * WM + mt * 16;
                af[mt][0] = f2tf(cA[(m + g) * LDS + ks * 8 + t4]);
                af[mt][1] = f2tf(cA[(m + g + 8) * LDS + ks * 8 + t4]);
                af[mt][2] = f2tf(cA[(m + g) * LDS + ks * 8 + t4 + 4]);
                af[mt][3] = f2tf(cA[(m + g + 8) * LDS + ks * 8 + t4 + 4]);
            }
#pragma unroll
            for (int nt = 0; nt < NT; nt++) {
                int n = wn * WN + nt * 8;
                bf[nt][0] = f2tf(cB[(n + g) * LDS + ks * 8 + t4]);
                bf[nt][1] = f2tf(cB[(n + g) * LDS + ks * 8 + t4 + 4]);
            }
#pragma unroll
            for (int mt = 0; mt < MT; mt++)
#pragma unroll
                for (int nt = 0; nt < NT; nt++) mma8(acc[mt][nt], af[mt], bf[nt]);
        }
    }
}

// ---------------------------------------------------------------------------
// Generic pipelined GEMM (batched, flexible C addressing, mask, bf16 out)
// ---------------------------------------------------------------------------
template <int BM, int BN, int WM, int WN, bool MASKED, bool BF16OUT, int TPB>
__global__ __launch_bounds__(TPB) void tgemm(
    const float* __restrict__ A, long sAb, int lda,
    const float* __restrict__ B, long sBb, int ldb,
    void* __restrict__ C, long sCb, long ldcm, long ldcn,
    const float* __restrict__ mask, int K, float alpha)
{
    extern __shared__ float sm[];
    float* sA = sm;
    float* sB = sm + 3 * BM * 36;
    constexpr int MT = WM / 16, NT = WN / 8, WNC = BN / WN;

    const long bm0 = (long)blockIdx.x * BM, bn0 = (long)blockIdx.y * BN;
    const float* Ab = A + (long)blockIdx.z * sAb + bm0 * lda;
    const float* Bb = B + (long)blockIdx.z * sBb + bn0 * ldb;

    float acc[MT][NT][4];
#pragma unroll
    for (int mt = 0; mt < MT; mt++)
#pragma unroll
        for (int nt = 0; nt < NT; nt++)
#pragma unroll
            for (int e = 0; e < 4; e++) acc[mt][nt][e] = 0.f;

    core_mma<BM, BN, WM, WN, TPB>(Ab, lda, Bb, ldb, K, sA, sB, acc);

    const int tid = threadIdx.x, lane = tid & 31, w = tid >> 5;
    const int g = lane >> 2, t4 = lane & 3;
    const int wn = w % WNC, wm = w / WNC;
#pragma unroll
    for (int mt = 0; mt < MT; mt++)
#pragma unroll
        for (int nt = 0; nt < NT; nt++)
#pragma unroll
            for (int e = 0; e < 4; e++) {
                long m = bm0 + wm * WM + mt * 16 + g + ((e >> 1) ? 8 : 0);
                long n = bn0 + wn * WN + nt * 8 + 2 * t4 + (e & 1);
                float v = acc[mt][nt][e] * alpha;
                if (MASKED) v += (1.f - mask[m & 1023]) * -1000000.f;
                long off = m * ldcm + n * ldcn + (long)blockIdx.z * sCb;
                if (BF16OUT)
                    ((__nv_bfloat16*)C)[off] = __float2bfloat16(v);
                else
                    ((float*)C)[off] = v;
            }
}

// ---------------------------------------------------------------------------
// Fused 4-projection GEMM, 128 threads, 64x64 warp tiles (2x2 warps).
// z=0 Q(+bias,tf32), z=1 K(tf32), z=2 V(transposed,tf32), z=3 G(sigmoid,f32)
// ---------------------------------------------------------------------------
__global__ __launch_bounds__(128, 2) void proj4_k(
    const float* __restrict__ s, const float* __restrict__ kin,
    const float* __restrict__ Wq, const float* __restrict__ bq,
    const float* __restrict__ Wk, const float* __restrict__ Wv,
    const float* __restrict__ Wg,
    float* __restrict__ Q, float* __restrict__ Kp,
    float* __restrict__ Vt, float* __restrict__ G)
{
    extern __shared__ float sm[];
    float* sA = sm;
    float* sB = sm + 3 * 128 * 36;
    const int z = blockIdx.z;
    const float* A = (z == 0 || z == 3) ? s : kin;
    const float* B = (z == 0) ? Wq : (z == 1) ? Wk : (z == 2) ? Wv : Wg;

    const long bm0 = (long)blockIdx.x * 128, bn0 = (long)blockIdx.y * 128;
    float acc[4][8][4];
#pragma unroll
    for (int mt = 0; mt < 4; mt++)
#pragma unroll
        for (int nt = 0; nt < 8; nt++)
#pragma unroll
            for (int e = 0; e < 4; e++) acc[mt][nt][e] = 0.f;

    core_mma<128, 128, 64, 64, 128>(A + bm0 * 1024, 1024, B + bn0 * 1024, 1024,
                                    1024, sA, sB, acc);

    const int tid = threadIdx.x, lane = tid & 31, w = tid >> 5;
    const int g = lane >> 2, t4 = lane & 3;
    const int wn = w & 1, wm = w >> 1;
#pragma unroll
    for (int mt = 0; mt < 4; mt++)
#pragma unroll
        for (int nt = 0; nt < 8; nt++)
#pragma unroll
            for (int e = 0; e < 4; e++) {
                long m = bm0 + wm * 64 + mt * 16 + g + ((e >> 1) ? 8 : 0);
                long n = bn0 + wn * 64 + nt * 8 + 2 * t4 + (e & 1);
                float v = acc[mt][nt][e];
                if (z == 0)      Q[m * 1024 + n] = __uint_as_float(f2tf(v + bq[n]));
                else if (z == 1) Kp[m * 1024 + n] = __uint_as_float(f2tf(v));
                else if (z == 2) Vt[n * 1024 + m] = __uint_as_float(f2tf(v));
                else             G[m * 1024 + n] = 1.f / (1.f + expf(-v));
            }
}

// ---------------------------------------------------------------------------
// Flash attention per (i-tile 64, head). K/V/Q arrive pre-rounded to tf32,
// Z arrives bf16. P overlays the current K buffer. Gate G in epilogue.
// smem: K0,K1,V0,V1 f32 [64][68]; Z0,Z1 bf16 [64][88].
// ---------------------------------------------------------------------------
#define FT 4352                     // 64*68 floats
#define ZT 5632                     // 64*88 bf16
__global__ __launch_bounds__(128) void flash_k(
    const float* __restrict__ Q, const float* __restrict__ K,
    const float* __restrict__ Vt, const __nv_bfloat16* __restrict__ Z,
    const float* __restrict__ G, float* __restrict__ O)
{
    extern __shared__ float sm[];
    __nv_bfloat16* smZ = (__nv_bfloat16*)(sm + 4 * FT);
    const int h = blockIdx.y;
    const long i0 = (long)blockIdx.x * 64;
    const int tid = threadIdx.x, w = tid >> 5, lane = tid & 31;
    const int g = lane >> 2, t4 = lane & 3;
    const int r0 = w * 16 + g;

    // persistent Q fragments (already tf32 bits)
    uint32_t qa[8][4];
    {
        const uint32_t* Qb = (const uint32_t*)(Q + i0 * 1024 + h * 64);
#pragma unroll
        for (int ks = 0; ks < 8; ks++) {
            qa[ks][0] = Qb[(long)r0 * 1024 + ks * 8 + t4];
            qa[ks][1] = Qb[(long)(r0 + 8) * 1024 + ks * 8 + t4];
            qa[ks][2] = Qb[(long)r0 * 1024 + ks * 8 + t4 + 4];
            qa[ks][3] = Qb[(long)(r0 + 8) * 1024 + ks * 8 + t4 + 4];
        }
    }

    float oacc[8][4];
#pragma unroll
    for (int nt = 0; nt < 8; nt++)
#pragma unroll
        for (int e = 0; e < 4; e++) oacc[nt][e] = 0.f;
    float m0 = -1e30f, m1 = -1e30f, l0 = 0.f, l1 = 0.f;

    auto stage = [&](int jt, int b) {
        const float* Ksrc = K + (long)jt * 64 * 1024 + h * 64;
        const float* Vsrc = Vt + (long)h * 65536 + jt * 64;
        const __nv_bfloat16* Zsrc = Z + (long)h * 1048576 + i0 * 1024 + jt * 64;
        float* dK = sm + b * FT;
        float* dV = sm + (2 + b) * FT;
        __nv_bfloat16* dZ = smZ + b * ZT;
#pragma unroll
        for (int idx = tid; idx < 1024; idx += 128) {
            int r = idx >> 4, c = (idx & 15) << 2;
            cpa16(dK + r * 68 + c, Ksrc + (long)r * 1024 + c);
            cpa16(dV + r * 68 + c, Vsrc + (long)r * 1024 + c);
        }
#pragma unroll
        for (int idx = tid; idx < 512; idx += 128) {
            int r = idx >> 3, c = (idx & 7) << 3;
            cpa16(dZ + r * 88 + c, Zsrc + (long)r * 1024 + c);
        }
    };

    stage(0, 0);
    cpa_commit();

    for (int jt = 0; jt < 16; jt++) {
        const int b = jt & 1;
        cpa_wait<0>();
        __syncthreads();
        if (jt < 15) { stage(jt + 1, b ^ 1); cpa_commit(); }

        const uint32_t* cK = (const uint32_t*)(sm + b * FT);
        const uint32_t* cV = (const uint32_t*)(sm + (2 + b) * FT);
        const __nv_bfloat16* cZ = smZ + b * ZT;

        // S = Q K^T
        float sacc[8][4];
#pragma unroll
        for (int nt = 0; nt < 8; nt++)
#pragma unroll
            for (int e = 0; e < 4; e++) sacc[nt][e] = 0.f;
#pragma unroll
        for (int ks = 0; ks < 8; ks++) {
#pragma unroll
            for (int nt = 0; nt < 8; nt++) {
                uint32_t bf[2];
                bf[0] = cK[(nt * 8 + g) * 68 + ks * 8 + t4];
                bf[1] = cK[(nt * 8 + g) * 68 + ks * 8 + t4 + 4];
                mma8(sacc[nt], qa[ks], bf);
            }
        }

        // scale + Z (bf16 -> f32)
#pragma unroll
        for (int nt = 0; nt < 8; nt++) {
            const float2 z0 = __bfloat1622float2(
                *reinterpret_cast<const __nv_bfloat162*>(&cZ[r0 * 88 + nt * 8 + 2 * t4]));
            const float2 z1 = __bfloat1622float2(
                *reinterpret_cast<const __nv_bfloat162*>(&cZ[(r0 + 8) * 88 + nt * 8 + 2 * t4]));
            sacc[nt][0] = fmaf(sacc[nt][0], 0.125f, z0.x);
            sacc[nt][1] = fmaf(sacc[nt][1], 0.125f, z0.y);
            sacc[nt][2] = fmaf(sacc[nt][2], 0.125f, z1.x);
            sacc[nt][3] = fmaf(sacc[nt][3], 0.125f, z1.y);
        }

        // online softmax
        float mx0 = -1e30f, mx1 = -1e30f;
#pragma unroll
        for (int nt = 0; nt < 8; nt++) {
            mx0 = fmaxf(mx0, fmaxf(sacc[nt][0], sacc[nt][1]));
            mx1 = fmaxf(mx1, fmaxf(sacc[nt][2], sacc[nt][3]));
        }
        mx0 = fmaxf(mx0, __shfl_xor_sync(0xFFFFFFFFu, mx0, 1));
        mx0 = fmaxf(mx0, __shfl_xor_sync(0xFFFFFFFFu, mx0, 2));
        mx1 = fmaxf(mx1, __shfl_xor_sync(0xFFFFFFFFu, mx1, 1));
        mx1 = fmaxf(mx1, __shfl_xor_sync(0xFFFFFFFFu, mx1, 2));

        const float mn0 = fmaxf(m0, mx0), mn1 = fmaxf(m1, mx1);
        const float a0 = __expf(m0 - mn0), a1 = __expf(m1 - mn1);
        m0 = mn0; m1 = mn1;

        float rs0 = 0.f, rs1 = 0.f;
#pragma unroll
        for (int nt = 0; nt < 8; nt++) {
            sacc[nt][0] = __expf(sacc[nt][0] - mn0);
            sacc[nt][1] = __expf(sacc[nt][1] - mn0);
            sacc[nt][2] = __expf(sacc[nt][2] - mn1);
            sacc[nt][3] = __expf(sacc[nt][3] - mn1);
            rs0 += sacc[nt][0] + sacc[nt][1];
            rs1 += sacc[nt][2] + sacc[nt][3];
        }
        rs0 += __shfl_xor_sync(0xFFFFFFFFu, rs0, 1);
        rs0 += __shfl_xor_sync(0xFFFFFFFFu, rs0, 2);
        rs1 += __shfl_xor_sync(0xFFFFFFFFu, rs1, 1);
        rs1 += __shfl_xor_sync(0xFFFFFFFFu, rs1, 2);
        l0 = l0 * a0 + rs0;
        l1 = l1 * a1 + rs1;
#pragma unroll
        for (int nt = 0; nt < 8; nt++) {
            oacc[nt][0] *= a0; oacc[nt][1] *= a0;
            oacc[nt][2] *= a1; oacc[nt][3] *= a1;
        }

        // P overlays current K buffer
        __syncthreads();
        uint32_t* pP = (uint32_t*)(sm + b * FT);
#pragma unroll
        for (int nt = 0; nt < 8; nt++) {
            uint2 p0 = make_uint2(f2tf(sacc[nt][0]), f2tf(sacc[nt][1]));
            uint2 p1 = make_uint2(f2tf(sacc[nt][2]), f2tf(sacc[nt][3]));
            *reinterpret_cast<uint2*>(&pP[r0 * 68 + nt * 8 + 2 * t4]) = p0;
            *reinterpret_cast<uint2*>(&pP[(r0 + 8) * 68 + nt * 8 + 2 * t4]) = p1;
        }
        __syncwarp();

        // O += P @ V
#pragma unroll
        for (int ks = 0; ks < 8; ks++) {
            uint32_t pa[4];
            pa[0] = pP[r0 * 68 + ks * 8 + t4];
            pa[1] = pP[(r0 + 8) * 68 + ks * 8 + t4];
            pa[2] = pP[r0 * 68 + ks * 8 + t4 + 4];
            pa[3] = pP[(r0 + 8) * 68 + ks * 8 + t4 + 4];
#pragma unroll
            for (int nt = 0; nt < 8; nt++) {
                uint32_t bf[2];
                bf[0] = cV[(nt * 8 + g) * 68 + ks * 8 + t4];
                bf[1] = cV[(nt * 8 + g) * 68 + ks * 8 + t4 + 4];
                mma8(oacc[nt], pa, bf);
            }
        }
    }

    // epilogue: o/l * G
    const float iv0 = 1.f / l0, iv1 = 1.f / l1;
#pragma unroll
    for (int nt = 0; nt < 8; nt++) {
        const int c = h * 64 + nt * 8 + 2 * t4;
        const long ro0 = (i0 + r0) * 1024 + c;
        const long ro1 = (i0 + r0 + 8) * 1024 + c;
        const float2 g0 = *reinterpret_cast<const float2*>(&G[ro0]);
        const float2 g1 = *reinterpret_cast<const float2*>(&G[ro1]);
        *reinterpret_cast<float2*>(&O[ro0]) =
            make_float2(oacc[nt][0] * iv0 * g0.x, oacc[nt][1] * iv0 * g0.y);
        *reinterpret_cast<float2*>(&O[ro1]) =
            make_float2(oacc[nt][2] * iv1 * g1.x, oacc[nt][3] * iv1 * g1.y);
    }
}

__global__ void wzt_k(const float* __restrict__ Wz, float* __restrict__ WzT)
{
    for (int idx = threadIdx.x; idx < 2048; idx += 256) {
        int c = idx >> 4, h = idx & 15;
        WzT[h * 128 + c] = Wz[c * 16 + h];
    }
}

// ---------------------------------------------------------------------------
// Launch
// ---------------------------------------------------------------------------
extern "C" void kernel_launch(void* const* d_in, const int* in_sizes, int n_in,
                              void* d_out, int out_size)
{
    const float* s    = (const float*)d_in[0];
    const float* k_in = (const float*)d_in[1];
    const float* mask = (const float*)d_in[2];
    const float* bias = (const float*)d_in[3];
    const float* Wq   = (const float*)d_in[4];
    const float* bq   = (const float*)d_in[5];
    const float* Wk   = (const float*)d_in[6];
    const float* Wv   = (const float*)d_in[7];
    const float* Wg   = (const float*)d_in[8];
    const float* Wo   = (const float*)d_in[9];
    const float* Wz   = (const float*)d_in[10];
    float* out = (float*)d_out;

    float *Q, *Kp, *Vt, *G, *O, *WzT;
    __nv_bfloat16* Z;
    cudaGetSymbolAddress((void**)&Q,   g_Q);
    cudaGetSymbolAddress((void**)&Kp,  g_K);
    cudaGetSymbolAddress((void**)&Vt,  g_Vt);
    cudaGetSymbolAddress((void**)&G,   g_G);
    cudaGetSymbolAddress((void**)&O,   g_O);
    cudaGetSymbolAddress((void**)&Z,   g_Z);
    cudaGetSymbolAddress((void**)&WzT, g_WzT);

    const int SM_PROJ  = 3 * (128 + 128) * 36 * 4;  // 110592
    const int SM_Z     = 3 * (128 + 16)  * 36 * 4;  //  62208
    const int SM_64128 = 3 * (64 + 128)  * 36 * 4;  //  82944
    const int SM_FLASH = 4 * FT * 4 + 2 * ZT * 2;   //  92160

    cudaFuncSetAttribute((const void*)proj4_k,
                         cudaFuncAttributeMaxDynamicSharedMemorySize, SM_PROJ);
    cudaFuncSetAttribute((const void*)tgemm<128, 16, 32, 8, true, true, 256>,
                         cudaFuncAttributeMaxDynamicSharedMemorySize, SM_Z);
    cudaFuncSetAttribute((const void*)tgemm<64, 128, 16, 64, false, false, 256>,
                         cudaFuncAttributeMaxDynamicSharedMemorySize, SM_64128);
    cudaFuncSetAttribute((const void*)flash_k,
                         cudaFuncAttributeMaxDynamicSharedMemorySize, SM_FLASH);

    // Q,K,V(t),G projections (outputs pre-rounded to tf32 where consumed by mma)
    proj4_k<<<dim3(8, 8, 4), dim3(128), SM_PROJ>>>(s, k_in, Wq, bq, Wk, Wv, Wg,
                                                   Q, Kp, Vt, G);

    // Z[h,i,j] = bias[i,j,:] @ Wz[:,h] + mask  (bf16 out)
    wzt_k<<<1, 256>>>(Wz, WzT);
    tgemm<128, 16, 32, 8, true, true, 256><<<dim3(8192, 1, 1), dim3(256), SM_Z>>>(
        bias, 0, 128, WzT, 0, 128, Z, 0, 1, 1048576, mask, 128, 1.f);

    // fused attention + gating
    flash_k<<<dim3(16, 16), dim3(128), SM_FLASH>>>(Q, Kp, Vt, Z, G, O);

    // out = O_gated @ Wo^T
    tgemm<64, 128, 16, 64, false, false, 256><<<dim3(16, 8, 1), dim3(256), SM_64128>>>(
        O, 0, 1024, Wo, 0, 1024, out, 0, 1024, 1, nullptr, 1024, 1.f);
}

// round 6
// speedup vs baseline: 2.1834x; 1.0669x over previous
#include <cuda_runtime.h>
#include <cuda_bf16.h>
#include <cstdint>

#define DINLINE __device__ __forceinline__

// ---------------------------------------------------------------------------
// helpers
// ---------------------------------------------------------------------------
DINLINE uint32_t f2tf(float x) {
    uint32_t r;
    asm("cvt.rna.tf32.f32 %0, %1;" : "=r"(r) : "f"(x));
    return r;
}

DINLINE void mma8(float c[4], const uint32_t a[4], const uint32_t b[2]) {
    asm volatile(
        "mma.sync.aligned.m16n8k8.row.col.f32.tf32.tf32.f32 "
        "{%0,%1,%2,%3}, {%4,%5,%6,%7}, {%8,%9}, {%0,%1,%2,%3};"
        : "+f"(c[0]), "+f"(c[1]), "+f"(c[2]), "+f"(c[3])
        : "r"(a[0]), "r"(a[1]), "r"(a[2]), "r"(a[3]), "r"(b[0]), "r"(b[1]));
}

DINLINE void cpa16(void* sm, const void* g) {
    uint32_t a = (uint32_t)__cvta_generic_to_shared(sm);
    asm volatile("cp.async.cg.shared.global [%0], [%1], 16;\n" :: "r"(a), "l"(g));
}
DINLINE void cpa_commit() { asm volatile("cp.async.commit_group;\n"); }
template <int N> DINLINE void cpa_wait() { asm volatile("cp.async.wait_group %0;\n" :: "n"(N)); }

// ---------------------------------------------------------------------------
// Scratch
// ---------------------------------------------------------------------------
__device__ float g_Q[1048576];     // tf32-rounded bits
__device__ float g_K[1048576];     // tf32-rounded bits
__device__ float g_Vt[1048576];    // [h][d][j], tf32-rounded bits
__device__ float g_G[1048576];
__device__ float g_O[1048576];
__device__ __nv_bfloat16 g_Z[16777216];  // [h][i][j] bf16

// ---------------------------------------------------------------------------
// Pipelined tf32 GEMM core (NT: both operands K-contiguous)
// ---------------------------------------------------------------------------
template <int BM, int BN, int WM, int WN, int TPB>
DINLINE void core_mma(const float* __restrict__ Ab, int lda,
                      const float* __restrict__ Bb, int ldb, int K,
                      float* sA, float* sB,
                      float (&acc)[WM / 16][WN / 8][4])
{
    constexpr int LDS = 36, BK = 32, S = 3;
    constexpr int WNC = BN / WN;
    constexpr int MT = WM / 16, NT = WN / 8;
    const int tid = threadIdx.x, lane = tid & 31, w = tid >> 5;
    const int g = lane >> 2, t4 = lane & 3;
    const int wn = w % WNC, wm = w / WNC;

    auto load_stage = [&](int tt, int st) {
        const float* Ak = Ab + tt * BK;
        const float* Bk = Bb + tt * BK;
        float* dA = sA + st * BM * LDS;
        float* dB = sB + st * BN * LDS;
#pragma unroll
        for (int idx = tid; idx < BM * 8; idx += TPB) {
            int r = idx >> 3, c = (idx & 7) << 2;
            cpa16(dA + r * LDS + c, Ak + (long)r * lda + c);
        }
#pragma unroll
        for (int idx = tid; idx < BN * 8; idx += TPB) {
            int r = idx >> 3, c = (idx & 7) << 2;
            cpa16(dB + r * LDS + c, Bk + (long)r * ldb + c);
        }
    };

    const int T = K / BK;
#pragma unroll
    for (int tt = 0; tt < S - 1; tt++) {
        if (tt < T) load_stage(tt, tt);
        cpa_commit();
    }

    for (int tt = 0; tt < T; tt++) {
        cpa_wait<S - 2>();
        __syncthreads();
        int tn = tt + S - 1;
        if (tn < T) load_stage(tn, tn % S);
        cpa_commit();

        const float* cA = sA + (tt % S) * BM * LDS;
        const float* cB = sB + (tt % S) * BN * LDS;
#pragma unroll
        for (int ks = 0; ks < 4; ks++) {
            uint32_t af[MT][4], bf[NT][2];
#pragma unroll
            for (int mt = 0; mt < MT; mt++) {
                int m = wm * WM + mt * 16;
                af[mt][0] = f2tf(cA[(m + g) * LDS + ks * 8 + t4]);
                af[mt][1] = f2tf(cA[(m + g + 8) * LDS + ks * 8 + t4]);
                af[mt][2] = f2tf(cA[(m + g) * LDS + ks * 8 + t4 + 4]);
                af[mt][3] = f2tf(cA[(m + g + 8) * LDS + ks * 8 + t4 + 4]);
            }
#pragma unroll
            for (int nt = 0; nt < NT; nt++) {
                int n = wn * WN + nt * 8;
                bf[nt][0] = f2tf(cB[(n + g) * LDS + ks * 8 + t4]);
                bf[nt][1] = f2tf(cB[(n + g) * LDS + ks * 8 + t4 + 4]);
            }
#pragma unroll
            for (int mt = 0; mt < MT; mt++)
#pragma unroll
                for (int nt = 0; nt < NT; nt++) mma8(acc[mt][nt], af[mt], bf[nt]);
        }
    }
}

// ---------------------------------------------------------------------------
// FAT KERNEL: proj4 (bx<256) + zgemm (bx>=256) in one launch so the
// compute-bound projections overlap the DRAM-bound bias*Wz projection.
// ---------------------------------------------------------------------------
__global__ __launch_bounds__(256, 2) void fused_pz_k(
    const float* __restrict__ s, const float* __restrict__ kin,
    const float* __restrict__ Wq, const float* __restrict__ bq,
    const float* __restrict__ Wk, const float* __restrict__ Wv,
    const float* __restrict__ Wg,
    const float* __restrict__ bias, const float* __restrict__ Wz,
    const float* __restrict__ mask,
    float* __restrict__ Q, float* __restrict__ Kp,
    float* __restrict__ Vt, float* __restrict__ G,
    __nv_bfloat16* __restrict__ Zout)
{
    extern __shared__ float sm[];
    const int bx = blockIdx.x;
    const int tid = threadIdx.x, lane = tid & 31, w = tid >> 5;
    const int g = lane >> 2, t4 = lane & 3;

    if (bx < 256) {
        // ---------------- proj path: 128x128 tile, warp 32x64 -------------
        float* sA = sm;
        float* sB = sm + 3 * 128 * 36;
        const int z = bx >> 6, rem = bx & 63;
        const int byy = rem >> 3, bxx = rem & 7;
        const float* A = (z == 0 || z == 3) ? s : kin;
        const float* B = (z == 0) ? Wq : (z == 1) ? Wk : (z == 2) ? Wv : Wg;

        const long bm0 = (long)bxx * 128, bn0 = (long)byy * 128;
        float acc[2][8][4];
#pragma unroll
        for (int mt = 0; mt < 2; mt++)
#pragma unroll
            for (int nt = 0; nt < 8; nt++)
#pragma unroll
                for (int e = 0; e < 4; e++) acc[mt][nt][e] = 0.f;

        core_mma<128, 128, 32, 64, 256>(A + bm0 * 1024, 1024, B + bn0 * 1024,
                                        1024, 1024, sA, sB, acc);

        const int wn = w & 1, wm = w >> 1;
#pragma unroll
        for (int mt = 0; mt < 2; mt++)
#pragma unroll
            for (int nt = 0; nt < 8; nt++)
#pragma unroll
                for (int e = 0; e < 4; e++) {
                    long m = bm0 + wm * 32 + mt * 16 + g + ((e >> 1) ? 8 : 0);
                    long n = bn0 + wn * 64 + nt * 8 + 2 * t4 + (e & 1);
                    float v = acc[mt][nt][e];
                    if (z == 0)      Q[m * 1024 + n] = __uint_as_float(f2tf(v + bq[n]));
                    else if (z == 1) Kp[m * 1024 + n] = __uint_as_float(f2tf(v));
                    else if (z == 2) Vt[n * 1024 + m] = __uint_as_float(f2tf(v));
                    else             G[m * 1024 + n] = 1.f / (1.f + expf(-v));
                }
    } else {
        // ---------------- zgemm path: Z[h, m] = bias[m,:] @ Wz[:,h] -------
        // 128 (i,j)-rows x 16 heads per CTA. WzT resident in smem [16][132].
        const int bz = bx - 256;
        float* sWzT = sm;                 // [16][132] (full K=128 resident)
        float* sA = sm + 16 * 132;        // 3 stages x [128][36]
        const float* Ab = bias + (long)bz * 128 * 128;

        for (int idx = tid; idx < 2048; idx += 256) {
            int c = idx >> 4, hh = idx & 15;
            sWzT[hh * 132 + c] = Wz[idx];    // Wz[c][hh] -> WzT[hh][c]
        }

        auto loadA = [&](int tt, int st) {
            const float* Ak = Ab + tt * 32;
            float* dA = sA + st * 128 * 36;
#pragma unroll
            for (int idx = tid; idx < 1024; idx += 256) {
                int r = idx >> 3, c = (idx & 7) << 2;
                cpa16(dA + r * 36 + c, Ak + (long)r * 128 + c);
            }
        };

        loadA(0, 0); cpa_commit();
        loadA(1, 1); cpa_commit();

        float acc[2][4];
#pragma unroll
        for (int nt = 0; nt < 2; nt++)
#pragma unroll
            for (int e = 0; e < 4; e++) acc[nt][e] = 0.f;

        const int wm = w;                  // 8 warps x 16 rows = 128
        for (int tt = 0; tt < 4; tt++) {
            cpa_wait<1>();
            __syncthreads();
            if (tt + 2 < 4) loadA(tt + 2, (tt + 2) % 3);
            cpa_commit();

            const float* cA = sA + (tt % 3) * 128 * 36;
#pragma unroll
            for (int ks = 0; ks < 4; ks++) {
                uint32_t af[4];
                af[0] = f2tf(cA[(wm * 16 + g) * 36 + ks * 8 + t4]);
                af[1] = f2tf(cA[(wm * 16 + g + 8) * 36 + ks * 8 + t4]);
                af[2] = f2tf(cA[(wm * 16 + g) * 36 + ks * 8 + t4 + 4]);
                af[3] = f2tf(cA[(wm * 16 + g + 8) * 36 + ks * 8 + t4 + 4]);
#pragma unroll
                for (int nt = 0; nt < 2; nt++) {
                    // B resident across K: offset by tt*32 within WzT row
                    uint32_t bf[2];
                    bf[0] = f2tf(sWzT[(nt * 8 + g) * 132 + tt * 32 + ks * 8 + t4]);
                    bf[1] = f2tf(sWzT[(nt * 8 + g) * 132 + tt * 32 + ks * 8 + t4 + 4]);
                    mma8(acc[nt], af, bf);
                }
            }
        }

#pragma unroll
        for (int nt = 0; nt < 2; nt++)
#pragma unroll
            for (int e = 0; e < 4; e++) {
                long m = (long)bz * 128 + wm * 16 + g + ((e >> 1) ? 8 : 0);
                long n = nt * 8 + 2 * t4 + (e & 1);
                float v = acc[nt][e] + (1.f - mask[m & 1023]) * -1000000.f;
                Zout[n * 1048576 + m] = __float2bfloat16(v);
            }
    }
}

// ---------------------------------------------------------------------------
// Generic pipelined GEMM (final output projection)
// ---------------------------------------------------------------------------
template <int BM, int BN, int WM, int WN, int TPB>
__global__ __launch_bounds__(TPB) void tgemm(
    const float* __restrict__ A, int lda,
    const float* __restrict__ B, int ldb,
    float* __restrict__ C, int K)
{
    extern __shared__ float sm[];
    float* sA = sm;
    float* sB = sm + 3 * BM * 36;
    constexpr int MT = WM / 16, NT = WN / 8, WNC = BN / WN;

    const long bm0 = (long)blockIdx.x * BM, bn0 = (long)blockIdx.y * BN;
    float acc[MT][NT][4];
#pragma unroll
    for (int mt = 0; mt < MT; mt++)
#pragma unroll
        for (int nt = 0; nt < NT; nt++)
#pragma unroll
            for (int e = 0; e < 4; e++) acc[mt][nt][e] = 0.f;

    core_mma<BM, BN, WM, WN, TPB>(A + bm0 * lda, lda, B + bn0 * ldb, ldb, K,
                                  sA, sB, acc);

    const int tid = threadIdx.x, lane = tid & 31, w = tid >> 5;
    const int g = lane >> 2, t4 = lane & 3;
    const int wn = w % WNC, wm = w / WNC;
#pragma unroll
    for (int mt = 0; mt < MT; mt++)
#pragma unroll
        for (int nt = 0; nt < NT; nt++)
#pragma unroll
            for (int e = 0; e < 4; e++) {
                long m = bm0 + wm * WM + mt * 16 + g + ((e >> 1) ? 8 : 0);
                long n = bn0 + wn * WN + nt * 8 + 2 * t4 + (e & 1);
                C[m * 1024 + n] = acc[mt][nt][e];
            }
}

// ---------------------------------------------------------------------------
// Flash attention per (i-tile 64, head). K/V/Q pre-rounded tf32, Z bf16.
// ---------------------------------------------------------------------------
#define FT 4352                     // 64*68 floats
#define ZT 5632                     // 64*88 bf16
__global__ __launch_bounds__(128) void flash_k(
    const float* __restrict__ Q, const float* __restrict__ K,
    const float* __restrict__ Vt, const __nv_bfloat16* __restrict__ Z,
    const float* __restrict__ G, float* __restrict__ O)
{
    extern __shared__ float sm[];
    __nv_bfloat16* smZ = (__nv_bfloat16*)(sm + 4 * FT);
    const int h = blockIdx.y;
    const long i0 = (long)blockIdx.x * 64;
    const int tid = threadIdx.x, w = tid >> 5, lane = tid & 31;
    const int g = lane >> 2, t4 = lane & 3;
    const int r0 = w * 16 + g;

    uint32_t qa[8][4];
    {
        const uint32_t* Qb = (const uint32_t*)(Q + i0 * 1024 + h * 64);
#pragma unroll
        for (int ks = 0; ks < 8; ks++) {
            qa[ks][0] = Qb[(long)r0 * 1024 + ks * 8 + t4];
            qa[ks][1] = Qb[(long)(r0 + 8) * 1024 + ks * 8 + t4];
            qa[ks][2] = Qb[(long)r0 * 1024 + ks * 8 + t4 + 4];
            qa[ks][3] = Qb[(long)(r0 + 8) * 1024 + ks * 8 + t4 + 4];
        }
    }

    float oacc[8][4];
#pragma unroll
    for (int nt = 0; nt < 8; nt++)
#pragma unroll
        for (int e = 0; e < 4; e++) oacc[nt][e] = 0.f;
    float m0 = -1e30f, m1 = -1e30f, l0 = 0.f, l1 = 0.f;

    auto stage = [&](int jt, int b) {
        const float* Ksrc = K + (long)jt * 64 * 1024 + h * 64;
        const float* Vsrc = Vt + (long)h * 65536 + jt * 64;
        const __nv_bfloat16* Zsrc = Z + (long)h * 1048576 + i0 * 1024 + jt * 64;
        float* dK = sm + b * FT;
        float* dV = sm + (2 + b) * FT;
        __nv_bfloat16* dZ = smZ + b * ZT;
#pragma unroll
        for (int idx = tid; idx < 1024; idx += 128) {
            int r = idx >> 4, c = (idx & 15) << 2;
            cpa16(dK + r * 68 + c, Ksrc + (long)r * 1024 + c);
            cpa16(dV + r * 68 + c, Vsrc + (long)r * 1024 + c);
        }
#pragma unroll
        for (int idx = tid; idx < 512; idx += 128) {
            int r = idx >> 3, c = (idx & 7) << 3;
            cpa16(dZ + r * 88 + c, Zsrc + (long)r * 1024 + c);
        }
    };

    stage(0, 0);
    cpa_commit();

    for (int jt = 0; jt < 16; jt++) {
        const int b = jt & 1;
        cpa_wait<0>();
        __syncthreads();
        if (jt < 15) { stage(jt + 1, b ^ 1); cpa_commit(); }

        const uint32_t* cK = (const uint32_t*)(sm + b * FT);
        const uint32_t* cV = (const uint32_t*)(sm + (2 + b) * FT);
        const __nv_bfloat16* cZ = smZ + b * ZT;

        float sacc[8][4];
#pragma unroll
        for (int nt = 0; nt < 8; nt++)
#pragma unroll
            for (int e = 0; e < 4; e++) sacc[nt][e] = 0.f;
#pragma unroll
        for (int ks = 0; ks < 8; ks++) {
#pragma unroll
            for (int nt = 0; nt < 8; nt++) {
                uint32_t bf[2];
                bf[0] = cK[(nt * 8 + g) * 68 + ks * 8 + t4];
                bf[1] = cK[(nt * 8 + g) * 68 + ks * 8 + t4 + 4];
                mma8(sacc[nt], qa[ks], bf);
            }
        }

#pragma unroll
        for (int nt = 0; nt < 8; nt++) {
            const float2 z0 = __bfloat1622float2(
                *reinterpret_cast<const __nv_bfloat162*>(&cZ[r0 * 88 + nt * 8 + 2 * t4]));
            const float2 z1 = __bfloat1622float2(
                *reinterpret_cast<const __nv_bfloat162*>(&cZ[(r0 + 8) * 88 + nt * 8 + 2 * t4]));
            sacc[nt][0] = fmaf(sacc[nt][0], 0.125f, z0.x);
            sacc[nt][1] = fmaf(sacc[nt][1], 0.125f, z0.y);
            sacc[nt][2] = fmaf(sacc[nt][2], 0.125f, z1.x);
            sacc[nt][3] = fmaf(sacc[nt][3], 0.125f, z1.y);
        }

        float mx0 = -1e30f, mx1 = -1e30f;
#pragma unroll
        for (int nt = 0; nt < 8; nt++) {
            mx0 = fmaxf(mx0, fmaxf(sacc[nt][0], sacc[nt][1]));
            mx1 = fmaxf(mx1, fmaxf(sacc[nt][2], sacc[nt][3]));
        }
        mx0 = fmaxf(mx0, __shfl_xor_sync(0xFFFFFFFFu, mx0, 1));
        mx0 = fmaxf(mx0, __shfl_xor_sync(0xFFFFFFFFu, mx0, 2));
        mx1 = fmaxf(mx1, __shfl_xor_sync(0xFFFFFFFFu, mx1, 1));
        mx1 = fmaxf(mx1, __shfl_xor_sync(0xFFFFFFFFu, mx1, 2));

        const float mn0 = fmaxf(m0, mx0), mn1 = fmaxf(m1, mx1);
        const float a0 = __expf(m0 - mn0), a1 = __expf(m1 - mn1);
        m0 = mn0; m1 = mn1;

        float rs0 = 0.f, rs1 = 0.f;
#pragma unroll
        for (int nt = 0; nt < 8; nt++) {
            sacc[nt][0] = __expf(sacc[nt][0] - mn0);
            sacc[nt][1] = __expf(sacc[nt][1] - mn0);
            sacc[nt][2] = __expf(sacc[nt][2] - mn1);
            sacc[nt][3] = __expf(sacc[nt][3] - mn1);
            rs0 += sacc[nt][0] + sacc[nt][1];
            rs1 += sacc[nt][2] + sacc[nt][3];
        }
        rs0 += __shfl_xor_sync(0xFFFFFFFFu, rs0, 1);
        rs0 += __shfl_xor_sync(0xFFFFFFFFu, rs0, 2);
        rs1 += __shfl_xor_sync(0xFFFFFFFFu, rs1, 1);
        rs1 += __shfl_xor_sync(0xFFFFFFFFu, rs1, 2);
        l0 = l0 * a0 + rs0;
        l1 = l1 * a1 + rs1;
#pragma unroll
        for (int nt = 0; nt < 8; nt++) {
            oacc[nt][0] *= a0; oacc[nt][1] *= a0;
            oacc[nt][2] *= a1; oacc[nt][3] *= a1;
        }

        __syncthreads();
        uint32_t* pP = (uint32_t*)(sm + b * FT);
#pragma unroll
        for (int nt = 0; nt < 8; nt++) {
            uint2 p0 = make_uint2(f2tf(sacc[nt][0]), f2tf(sacc[nt][1]));
            uint2 p1 = make_uint2(f2tf(sacc[nt][2]), f2tf(sacc[nt][3]));
            *reinterpret_cast<uint2*>(&pP[r0 * 68 + nt * 8 + 2 * t4]) = p0;
            *reinterpret_cast<uint2*>(&pP[(r0 + 8) * 68 + nt * 8 + 2 * t4]) = p1;
        }
        __syncwarp();

#pragma unroll
        for (int ks = 0; ks < 8; ks++) {
            uint32_t pa[4];
            pa[0] = pP[r0 * 68 + ks * 8 + t4];
            pa[1] = pP[(r0 + 8) * 68 + ks * 8 + t4];
            pa[2] = pP[r0 * 68 + ks * 8 + t4 + 4];
            pa[3] = pP[(r0 + 8) * 68 + ks * 8 + t4 + 4];
#pragma unroll
            for (int nt = 0; nt < 8; nt++) {
                uint32_t bf[2];
                bf[0] = cV[(nt * 8 + g) * 68 + ks * 8 + t4];
                bf[1] = cV[(nt * 8 + g) * 68 + ks * 8 + t4 + 4];
                mma8(oacc[nt], pa, bf);
            }
        }
    }

    const float iv0 = 1.f / l0, iv1 = 1.f / l1;
#pragma unroll
    for (int nt = 0; nt < 8; nt++) {
        const int c = h * 64 + nt * 8 + 2 * t4;
        const long ro0 = (i0 + r0) * 1024 + c;
        const long ro1 = (i0 + r0 + 8) * 1024 + c;
        const float2 g0 = *reinterpret_cast<const float2*>(&G[ro0]);
        const float2 g1 = *reinterpret_cast<const float2*>(&G[ro1]);
        *reinterpret_cast<float2*>(&O[ro0]) =
            make_float2(oacc[nt][0] * iv0 * g0.x, oacc[nt][1] * iv0 * g0.y);
        *reinterpret_cast<float2*>(&O[ro1]) =
            make_float2(oacc[nt][2] * iv1 * g1.x, oacc[nt][3] * iv1 * g1.y);
    }
}

// ---------------------------------------------------------------------------
// Launch
// ---------------------------------------------------------------------------
extern "C" void kernel_launch(void* const* d_in, const int* in_sizes, int n_in,
                              void* d_out, int out_size)
{
    const float* s    = (const float*)d_in[0];
    const float* k_in = (const float*)d_in[1];
    const float* mask = (const float*)d_in[2];
    const float* bias = (const float*)d_in[3];
    const float* Wq   = (const float*)d_in[4];
    const float* bq   = (const float*)d_in[5];
    const float* Wk   = (const float*)d_in[6];
    const float* Wv   = (const float*)d_in[7];
    const float* Wg   = (const float*)d_in[8];
    const float* Wo   = (const float*)d_in[9];
    const float* Wz   = (const float*)d_in[10];
    float* out = (float*)d_out;

    float *Q, *Kp, *Vt, *G, *O;
    __nv_bfloat16* Z;
    cudaGetSymbolAddress((void**)&Q,   g_Q);
    cudaGetSymbolAddress((void**)&Kp,  g_K);
    cudaGetSymbolAddress((void**)&Vt,  g_Vt);
    cudaGetSymbolAddress((void**)&G,   g_G);
    cudaGetSymbolAddress((void**)&O,   g_O);
    cudaGetSymbolAddress((void**)&Z,   g_Z);

    const int SM_FAT   = 3 * (128 + 128) * 36 * 4;  // 110592
    const int SM_6464  = 3 * (64 + 64) * 36 * 4;    //  55296
    const int SM_FLASH = 4 * FT * 4 + 2 * ZT * 2;   //  92160

    cudaFuncSetAttribute((const void*)fused_pz_k,
                         cudaFuncAttributeMaxDynamicSharedMemorySize, SM_FAT);
    cudaFuncSetAttribute((const void*)tgemm<64, 64, 16, 32, 256>,
                         cudaFuncAttributeMaxDynamicSharedMemorySize, SM_6464);
    cudaFuncSetAttribute((const void*)flash_k,
                         cudaFuncAttributeMaxDynamicSharedMemorySize, SM_FLASH);

    // proj4 (256 CTAs) + zgemm (8192 CTAs) overlapped in one launch
    fused_pz_k<<<8448, 256, SM_FAT>>>(s, k_in, Wq, bq, Wk, Wv, Wg,
                                      bias, Wz, mask, Q, Kp, Vt, G, Z);

    // fused attention + gating
    flash_k<<<dim3(16, 16), 128, SM_FLASH>>>(Q, Kp, Vt, Z, G, O);

    // out = O_gated @ Wo^T
    tgemm<64, 64, 16, 32, 256><<<dim3(16, 16), 256, SM_6464>>>(
        O, 1024, Wo, 1024, out, 1024);
}

// round 7
// speedup vs baseline: 2.2057x; 1.0102x over previous
#include <cuda_runtime.h>
#include <cuda_bf16.h>
#include <cstdint>

#define DINLINE __device__ __forceinline__

// ---------------------------------------------------------------------------
// helpers
// ---------------------------------------------------------------------------
DINLINE uint32_t f2tf(float x) {
    uint32_t r;
    asm("cvt.rna.tf32.f32 %0, %1;" : "=r"(r) : "f"(x));
    return r;
}

DINLINE void mma8(float c[4], const uint32_t a[4], const uint32_t b[2]) {
    asm volatile(
        "mma.sync.aligned.m16n8k8.row.col.f32.tf32.tf32.f32 "
        "{%0,%1,%2,%3}, {%4,%5,%6,%7}, {%8,%9}, {%0,%1,%2,%3};"
        : "+f"(c[0]), "+f"(c[1]), "+f"(c[2]), "+f"(c[3])
        : "r"(a[0]), "r"(a[1]), "r"(a[2]), "r"(a[3]), "r"(b[0]), "r"(b[1]));
}

DINLINE void cpa16(void* sm, const void* g) {
    uint32_t a = (uint32_t)__cvta_generic_to_shared(sm);
    asm volatile("cp.async.cg.shared.global [%0], [%1], 16;\n" :: "r"(a), "l"(g));
}
DINLINE void cpa_commit() { asm volatile("cp.async.commit_group;\n"); }
template <int N> DINLINE void cpa_wait() { asm volatile("cp.async.wait_group %0;\n" :: "n"(N)); }

// ---------------------------------------------------------------------------
// Scratch
// ---------------------------------------------------------------------------
__device__ float g_Q[1048576];     // tf32-rounded bits
__device__ float g_K[1048576];     // tf32-rounded bits
__device__ float g_Vt[1048576];    // [h][d][j], tf32-rounded bits
__device__ float g_G[1048576];
__device__ float g_O[1048576];
__device__ __nv_bfloat16 g_Z[16777216];  // [h][i][j] bf16

// ---------------------------------------------------------------------------
// Pipelined tf32 GEMM core (NT: both operands K-contiguous)
// ---------------------------------------------------------------------------
template <int BM, int BN, int WM, int WN, int TPB>
DINLINE void core_mma(const float* __restrict__ Ab, int lda,
                      const float* __restrict__ Bb, int ldb, int K,
                      float* sA, float* sB,
                      float (&acc)[WM / 16][WN / 8][4])
{
    constexpr int LDS = 36, BK = 32, S = 3;
    constexpr int WNC = BN / WN;
    constexpr int MT = WM / 16, NT = WN / 8;
    const int tid = threadIdx.x, lane = tid & 31, w = tid >> 5;
    const int g = lane >> 2, t4 = lane & 3;
    const int wn = w % WNC, wm = w / WNC;

    auto load_stage = [&](int tt, int st) {
        const float* Ak = Ab + tt * BK;
        const float* Bk = Bb + tt * BK;
        float* dA = sA + st * BM * LDS;
        float* dB = sB + st * BN * LDS;
#pragma unroll
        for (int idx = tid; idx < BM * 8; idx += TPB) {
            int r = idx >> 3, c = (idx & 7) << 2;
            cpa16(dA + r * LDS + c, Ak + (long)r * lda + c);
        }
#pragma unroll
        for (int idx = tid; idx < BN * 8; idx += TPB) {
            int r = idx >> 3, c = (idx & 7) << 2;
            cpa16(dB + r * LDS + c, Bk + (long)r * ldb + c);
        }
    };

    const int T = K / BK;
#pragma unroll
    for (int tt = 0; tt < S - 1; tt++) {
        if (tt < T) load_stage(tt, tt);
        cpa_commit();
    }

    for (int tt = 0; tt < T; tt++) {
        cpa_wait<S - 2>();
        __syncthreads();
        int tn = tt + S - 1;
        if (tn < T) load_stage(tn, tn % S);
        cpa_commit();

        const float* cA = sA + (tt % S) * BM * LDS;
        const float* cB = sB + (tt % S) * BN * LDS;
#pragma unroll
        for (int ks = 0; ks < 4; ks++) {
            uint32_t af[MT][4], bf[NT][2];
#pragma unroll
            for (int mt = 0; mt < MT; mt++) {
                int m = wm * WM + mt * 16;
                af[mt][0] = f2tf(cA[(m + g) * LDS + ks * 8 + t4]);
                af[mt][1] = f2tf(cA[(m + g + 8) * LDS + ks * 8 + t4]);
                af[mt][2] = f2tf(cA[(m + g) * LDS + ks * 8 + t4 + 4]);
                af[mt][3] = f2tf(cA[(m + g + 8) * LDS + ks * 8 + t4 + 4]);
            }
#pragma unroll
            for (int nt = 0; nt < NT; nt++) {
                int n = wn * WN + nt * 8;
                bf[nt][0] = f2tf(cB[(n + g) * LDS + ks * 8 + t4]);
                bf[nt][1] = f2tf(cB[(n + g) * LDS + ks * 8 + t4 + 4]);
            }
#pragma unroll
            for (int mt = 0; mt < MT; mt++)
#pragma unroll
                for (int nt = 0; nt < NT; nt++) mma8(acc[mt][nt], af[mt], bf[nt]);
        }
    }
}

// ---------------------------------------------------------------------------
// FAT KERNEL: persistent proj CTAs (bx<128, 2 tiles each) + zgemm (bx>=128).
// Wave 1 = 128 proj + 168 zgemm slots -> every SM streams bias under proj.
// ---------------------------------------------------------------------------
__global__ __launch_bounds__(256, 2) void fused_pz_k(
    const float* __restrict__ s, const float* __restrict__ kin,
    const float* __restrict__ Wq, const float* __restrict__ bq,
    const float* __restrict__ Wk, const float* __restrict__ Wv,
    const float* __restrict__ Wg,
    const float* __restrict__ bias, const float* __restrict__ Wz,
    const float* __restrict__ mask,
    float* __restrict__ Q, float* __restrict__ Kp,
    float* __restrict__ Vt, float* __restrict__ G,
    __nv_bfloat16* __restrict__ Zout)
{
    extern __shared__ float sm[];
    const int bx = blockIdx.x;
    const int tid = threadIdx.x, lane = tid & 31, w = tid >> 5;
    const int g = lane >> 2, t4 = lane & 3;

    if (bx < 128) {
        // ------------- proj path: 2 tiles of 128x128, warp 32x64 ----------
        float* sA = sm;
        float* sB = sm + 3 * 128 * 36;
        const int wn = w & 1, wm = w >> 1;

#pragma unroll 1
        for (int t = bx; t < 256; t += 128) {
            const int z = t >> 6, rem = t & 63;
            const int byy = rem >> 3, bxx = rem & 7;
            const float* A = (z == 0 || z == 3) ? s : kin;
            const float* B = (z == 0) ? Wq : (z == 1) ? Wk : (z == 2) ? Wv : Wg;

            const long bm0 = (long)bxx * 128, bn0 = (long)byy * 128;
            float acc[2][8][4];
#pragma unroll
            for (int mt = 0; mt < 2; mt++)
#pragma unroll
                for (int nt = 0; nt < 8; nt++)
#pragma unroll
                    for (int e = 0; e < 4; e++) acc[mt][nt][e] = 0.f;

            core_mma<128, 128, 32, 64, 256>(A + bm0 * 1024, 1024,
                                            B + bn0 * 1024, 1024, 1024,
                                            sA, sB, acc);

#pragma unroll
            for (int mt = 0; mt < 2; mt++)
#pragma unroll
                for (int nt = 0; nt < 8; nt++)
#pragma unroll
                    for (int e = 0; e < 4; e++) {
                        long m = bm0 + wm * 32 + mt * 16 + g + ((e >> 1) ? 8 : 0);
                        long n = bn0 + wn * 64 + nt * 8 + 2 * t4 + (e & 1);
                        float v = acc[mt][nt][e];
                        if (z == 0)      Q[m * 1024 + n] = __uint_as_float(f2tf(v + bq[n]));
                        else if (z == 1) Kp[m * 1024 + n] = __uint_as_float(f2tf(v));
                        else if (z == 2) Vt[n * 1024 + m] = __uint_as_float(f2tf(v));
                        else             G[m * 1024 + n] = 1.f / (1.f + expf(-v));
                    }
            __syncthreads();   // protect smem before next tile's stage-0 loads
        }
    } else {
        // ---------------- zgemm path: Z[h, m] = bias[m,:] @ Wz[:,h] -------
        const int bz = bx - 128;
        float* sWzT = sm;                 // [16][132] (full K=128 resident)
        float* sA = sm + 16 * 132;        // 3 stages x [128][36]
        const float* Ab = bias + (long)bz * 128 * 128;

        for (int idx = tid; idx < 2048; idx += 256) {
            int c = idx >> 4, hh = idx & 15;
            sWzT[hh * 132 + c] = Wz[idx];    // Wz[c][hh] -> WzT[hh][c]
        }

        auto loadA = [&](int tt, int st) {
            const float* Ak = Ab + tt * 32;
            float* dA = sA + st * 128 * 36;
#pragma unroll
            for (int idx = tid; idx < 1024; idx += 256) {
                int r = idx >> 3, c = (idx & 7) << 2;
                cpa16(dA + r * 36 + c, Ak + (long)r * 128 + c);
            }
        };

        loadA(0, 0); cpa_commit();
        loadA(1, 1); cpa_commit();

        float acc[2][4];
#pragma unroll
        for (int nt = 0; nt < 2; nt++)
#pragma unroll
            for (int e = 0; e < 4; e++) acc[nt][e] = 0.f;

        const int wm = w;                  // 8 warps x 16 rows = 128
        for (int tt = 0; tt < 4; tt++) {
            cpa_wait<1>();
            __syncthreads();
            if (tt + 2 < 4) loadA(tt + 2, (tt + 2) % 3);
            cpa_commit();

            const float* cA = sA + (tt % 3) * 128 * 36;
#pragma unroll
            for (int ks = 0; ks < 4; ks++) {
                uint32_t af[4];
                af[0] = f2tf(cA[(wm * 16 + g) * 36 + ks * 8 + t4]);
                af[1] = f2tf(cA[(wm * 16 + g + 8) * 36 + ks * 8 + t4]);
                af[2] = f2tf(cA[(wm * 16 + g) * 36 + ks * 8 + t4 + 4]);
                af[3] = f2tf(cA[(wm * 16 + g + 8) * 36 + ks * 8 + t4 + 4]);
#pragma unroll
                for (int nt = 0; nt < 2; nt++) {
                    uint32_t bf[2];
                    bf[0] = f2tf(sWzT[(nt * 8 + g) * 132 + tt * 32 + ks * 8 + t4]);
                    bf[1] = f2tf(sWzT[(nt * 8 + g) * 132 + tt * 32 + ks * 8 + t4 + 4]);
                    mma8(acc[nt], af, bf);
                }
            }
        }

#pragma unroll
        for (int nt = 0; nt < 2; nt++)
#pragma unroll
            for (int e = 0; e < 4; e++) {
                long m = (long)bz * 128 + wm * 16 + g + ((e >> 1) ? 8 : 0);
                long n = nt * 8 + 2 * t4 + (e & 1);
                float v = acc[nt][e] + (1.f - mask[m & 1023]) * -1000000.f;
                Zout[n * 1048576 + m] = __float2bfloat16(v);
            }
    }
}

// ---------------------------------------------------------------------------
// Generic pipelined GEMM (final output projection)
// ---------------------------------------------------------------------------
template <int BM, int BN, int WM, int WN, int TPB>
__global__ __launch_bounds__(TPB) void tgemm(
    const float* __restrict__ A, int lda,
    const float* __restrict__ B, int ldb,
    float* __restrict__ C, int K)
{
    extern __shared__ float sm[];
    float* sA = sm;
    float* sB = sm + 3 * BM * 36;
    constexpr int MT = WM / 16, NT = WN / 8, WNC = BN / WN;

    const long bm0 = (long)blockIdx.x * BM, bn0 = (long)blockIdx.y * BN;
    float acc[MT][NT][4];
#pragma unroll
    for (int mt = 0; mt < MT; mt++)
#pragma unroll
        for (int nt = 0; nt < NT; nt++)
#pragma unroll
            for (int e = 0; e < 4; e++) acc[mt][nt][e] = 0.f;

    core_mma<BM, BN, WM, WN, TPB>(A + bm0 * lda, lda, B + bn0 * ldb, ldb, K,
                                  sA, sB, acc);

    const int tid = threadIdx.x, lane = tid & 31, w = tid >> 5;
    const int g = lane >> 2, t4 = lane & 3;
    const int wn = w % WNC, wm = w / WNC;
#pragma unroll
    for (int mt = 0; mt < MT; mt++)
#pragma unroll
        for (int nt = 0; nt < NT; nt++)
#pragma unroll
            for (int e = 0; e < 4; e++) {
                long m = bm0 + wm * WM + mt * 16 + g + ((e >> 1) ? 8 : 0);
                long n = bn0 + wn * WN + nt * 8 + 2 * t4 + (e & 1);
                C[m * 1024 + n] = acc[mt][nt][e];
            }
}

// ---------------------------------------------------------------------------
// Flash attention per (i-tile 64, head). K/V/Q pre-rounded tf32, Z bf16.
// ---------------------------------------------------------------------------
#define FT 4352                     // 64*68 floats
#define ZT 5632                     // 64*88 bf16
__global__ __launch_bounds__(128) void flash_k(
    const float* __restrict__ Q, const float* __restrict__ K,
    const float* __restrict__ Vt, const __nv_bfloat16* __restrict__ Z,
    const float* __restrict__ G, float* __restrict__ O)
{
    extern __shared__ float sm[];
    __nv_bfloat16* smZ = (__nv_bfloat16*)(sm + 4 * FT);
    const int h = blockIdx.y;
    const long i0 = (long)blockIdx.x * 64;
    const int tid = threadIdx.x, w = tid >> 5, lane = tid & 31;
    const int g = lane >> 2, t4 = lane & 3;
    const int r0 = w * 16 + g;

    uint32_t qa[8][4];
    {
        const uint32_t* Qb = (const uint32_t*)(Q + i0 * 1024 + h * 64);
#pragma unroll
        for (int ks = 0; ks < 8; ks++) {
            qa[ks][0] = Qb[(long)r0 * 1024 + ks * 8 + t4];
            qa[ks][1] = Qb[(long)(r0 + 8) * 1024 + ks * 8 + t4];
            qa[ks][2] = Qb[(long)r0 * 1024 + ks * 8 + t4 + 4];
            qa[ks][3] = Qb[(long)(r0 + 8) * 1024 + ks * 8 + t4 + 4];
        }
    }

    float oacc[8][4];
#pragma unroll
    for (int nt = 0; nt < 8; nt++)
#pragma unroll
        for (int e = 0; e < 4; e++) oacc[nt][e] = 0.f;
    float m0 = -1e30f, m1 = -1e30f, l0 = 0.f, l1 = 0.f;

    auto stage = [&](int jt, int b) {
        const float* Ksrc = K + (long)jt * 64 * 1024 + h * 64;
        const float* Vsrc = Vt + (long)h * 65536 + jt * 64;
        const __nv_bfloat16* Zsrc = Z + (long)h * 1048576 + i0 * 1024 + jt * 64;
        float* dK = sm + b * FT;
        float* dV = sm + (2 + b) * FT;
        __nv_bfloat16* dZ = smZ + b * ZT;
#pragma unroll
        for (int idx = tid; idx < 1024; idx += 128) {
            int r = idx >> 4, c = (idx & 15) << 2;
            cpa16(dK + r * 68 + c, Ksrc + (long)r * 1024 + c);
            cpa16(dV + r * 68 + c, Vsrc + (long)r * 1024 + c);
        }
#pragma unroll
        for (int idx = tid; idx < 512; idx += 128) {
            int r = idx >> 3, c = (idx & 7) << 3;
            cpa16(dZ + r * 88 + c, Zsrc + (long)r * 1024 + c);
        }
    };

    stage(0, 0);
    cpa_commit();

    for (int jt = 0; jt < 16; jt++) {
        const int b = jt & 1;
        cpa_wait<0>();
        __syncthreads();
        if (jt < 15) { stage(jt + 1, b ^ 1); cpa_commit(); }

        const uint32_t* cK = (const uint32_t*)(sm + b * FT);
        const uint32_t* cV = (const uint32_t*)(sm + (2 + b) * FT);
        const __nv_bfloat16* cZ = smZ + b * ZT;

        float sacc[8][4];
#pragma unroll
        for (int nt = 0; nt < 8; nt++)
#pragma unroll
            for (int e = 0; e < 4; e++) sacc[nt][e] = 0.f;
#pragma unroll
        for (int ks = 0; ks < 8; ks++) {
#pragma unroll
            for (int nt = 0; nt < 8; nt++) {
                uint32_t bf[2];
                bf[0] = cK[(nt * 8 + g) * 68 + ks * 8 + t4];
                bf[1] = cK[(nt * 8 + g) * 68 + ks * 8 + t4 + 4];
                mma8(sacc[nt], qa[ks], bf);
            }
        }

#pragma unroll
        for (int nt = 0; nt < 8; nt++) {
            const float2 z0 = __bfloat1622float2(
                *reinterpret_cast<const __nv_bfloat162*>(&cZ[r0 * 88 + nt * 8 + 2 * t4]));
            const float2 z1 = __bfloat1622float2(
                *reinterpret_cast<const __nv_bfloat162*>(&cZ[(r0 + 8) * 88 + nt * 8 + 2 * t4]));
            sacc[nt][0] = fmaf(sacc[nt][0], 0.125f, z0.x);
            sacc[nt][1] = fmaf(sacc[nt][1], 0.125f, z0.y);
            sacc[nt][2] = fmaf(sacc[nt][2], 0.125f, z1.x);
            sacc[nt][3] = fmaf(sacc[nt][3], 0.125f, z1.y);
        }

        float mx0 = -1e30f, mx1 = -1e30f;
#pragma unroll
        for (int nt = 0; nt < 8; nt++) {
            mx0 = fmaxf(mx0, fmaxf(sacc[nt][0], sacc[nt][1]));
            mx1 = fmaxf(mx1, fmaxf(sacc[nt][2], sacc[nt][3]));
        }
        mx0 = fmaxf(mx0, __shfl_xor_sync(0xFFFFFFFFu, mx0, 1));
        mx0 = fmaxf(mx0, __shfl_xor_sync(0xFFFFFFFFu, mx0, 2));
        mx1 = fmaxf(mx1, __shfl_xor_sync(0xFFFFFFFFu, mx1, 1));
        mx1 = fmaxf(mx1, __shfl_xor_sync(0xFFFFFFFFu, mx1, 2));

        const float mn0 = fmaxf(m0, mx0), mn1 = fmaxf(m1, mx1);
        const float a0 = __expf(m0 - mn0), a1 = __expf(m1 - mn1);
        m0 = mn0; m1 = mn1;

        float rs0 = 0.f, rs1 = 0.f;
#pragma unroll
        for (int nt = 0; nt < 8; nt++) {
            sacc[nt][0] = __expf(sacc[nt][0] - mn0);
            sacc[nt][1] = __expf(sacc[nt][1] - mn0);
            sacc[nt][2] = __expf(sacc[nt][2] - mn1);
            sacc[nt][3] = __expf(sacc[nt][3] - mn1);
            rs0 += sacc[nt][0] + sacc[nt][1];
            rs1 += sacc[nt][2] + sacc[nt][3];
        }
        rs0 += __shfl_xor_sync(0xFFFFFFFFu, rs0, 1);
        rs0 += __shfl_xor_sync(0xFFFFFFFFu, rs0, 2);
        rs1 += __shfl_xor_sync(0xFFFFFFFFu, rs1, 1);
        rs1 += __shfl_xor_sync(0xFFFFFFFFu, rs1, 2);
        l0 = l0 * a0 + rs0;
        l1 = l1 * a1 + rs1;
#pragma unroll
        for (int nt = 0; nt < 8; nt++) {
            oacc[nt][0] *= a0; oacc[nt][1] *= a0;
            oacc[nt][2] *= a1; oacc[nt][3] *= a1;
        }

        __syncthreads();
        uint32_t* pP = (uint32_t*)(sm + b * FT);
#pragma unroll
        for (int nt = 0; nt < 8; nt++) {
            uint2 p0 = make_uint2(f2tf(sacc[nt][0]), f2tf(sacc[nt][1]));
            uint2 p1 = make_uint2(f2tf(sacc[nt][2]), f2tf(sacc[nt][3]));
            *reinterpret_cast<uint2*>(&pP[r0 * 68 + nt * 8 + 2 * t4]) = p0;
            *reinterpret_cast<uint2*>(&pP[(r0 + 8) * 68 + nt * 8 + 2 * t4]) = p1;
        }
        __syncwarp();

#pragma unroll
        for (int ks = 0; ks < 8; ks++) {
            uint32_t pa[4];
            pa[0] = pP[r0 * 68 + ks * 8 + t4];
            pa[1] = pP[(r0 + 8) * 68 + ks * 8 + t4];
            pa[2] = pP[r0 * 68 + ks * 8 + t4 + 4];
            pa[3] = pP[(r0 + 8) * 68 + ks * 8 + t4 + 4];
#pragma unroll
            for (int nt = 0; nt < 8; nt++) {
                uint32_t bf[2];
                bf[0] = cV[(nt * 8 + g) * 68 + ks * 8 + t4];
                bf[1] = cV[(nt * 8 + g) * 68 + ks * 8 + t4 + 4];
                mma8(oacc[nt], pa, bf);
            }
        }
    }

    const float iv0 = 1.f / l0, iv1 = 1.f / l1;
#pragma unroll
    for (int nt = 0; nt < 8; nt++) {
        const int c = h * 64 + nt * 8 + 2 * t4;
        const long ro0 = (i0 + r0) * 1024 + c;
        const long ro1 = (i0 + r0 + 8) * 1024 + c;
        const float2 g0 = *reinterpret_cast<const float2*>(&G[ro0]);
        const float2 g1 = *reinterpret_cast<const float2*>(&G[ro1]);
        *reinterpret_cast<float2*>(&O[ro0]) =
            make_float2(oacc[nt][0] * iv0 * g0.x, oacc[nt][1] * iv0 * g0.y);
        *reinterpret_cast<float2*>(&O[ro1]) =
            make_float2(oacc[nt][2] * iv1 * g1.x, oacc[nt][3] * iv1 * g1.y);
    }
}

// ---------------------------------------------------------------------------
// Launch
// ---------------------------------------------------------------------------
extern "C" void kernel_launch(void* const* d_in, const int* in_sizes, int n_in,
                              void* d_out, int out_size)
{
    const float* s    = (const float*)d_in[0];
    const float* k_in = (const float*)d_in[1];
    const float* mask = (const float*)d_in[2];
    const float* bias = (const float*)d_in[3];
    const float* Wq   = (const float*)d_in[4];
    const float* bq   = (const float*)d_in[5];
    const float* Wk   = (const float*)d_in[6];
    const float* Wv   = (const float*)d_in[7];
    const float* Wg   = (const float*)d_in[8];
    const float* Wo   = (const float*)d_in[9];
    const float* Wz   = (const float*)d_in[10];
    float* out = (float*)d_out;

    float *Q, *Kp, *Vt, *G, *O;
    __nv_bfloat16* Z;
    cudaGetSymbolAddress((void**)&Q,   g_Q);
    cudaGetSymbolAddress((void**)&Kp,  g_K);
    cudaGetSymbolAddress((void**)&Vt,  g_Vt);
    cudaGetSymbolAddress((void**)&G,   g_G);
    cudaGetSymbolAddress((void**)&O,   g_O);
    cudaGetSymbolAddress((void**)&Z,   g_Z);

    const int SM_FAT   = 3 * (128 + 128) * 36 * 4;  // 110592
    const int SM_6464  = 3 * (64 + 64) * 36 * 4;    //  55296
    const int SM_FLASH = 4 * FT * 4 + 2 * ZT * 2;   //  92160

    cudaFuncSetAttribute((const void*)fused_pz_k,
                         cudaFuncAttributeMaxDynamicSharedMemorySize, SM_FAT);
    cudaFuncSetAttribute((const void*)tgemm<64, 64, 16, 32, 256>,
                         cudaFuncAttributeMaxDynamicSharedMemorySize, SM_6464);
    cudaFuncSetAttribute((const void*)flash_k,
                         cudaFuncAttributeMaxDynamicSharedMemorySize, SM_FLASH);

    // 128 persistent proj CTAs (2 tiles each) + 8192 zgemm CTAs, overlapped
    fused_pz_k<<<8320, 256, SM_FAT>>>(s, k_in, Wq, bq, Wk, Wv, Wg,
                                      bias, Wz, mask, Q, Kp, Vt, G, Z);

    // fused attention + gating
    flash_k<<<dim3(16, 16), 128, SM_FLASH>>>(Q, Kp, Vt, Z, G, O);

    // out = O_gated @ Wo^T
    tgemm<64, 64, 16, 32, 256><<<dim3(16, 16), 256, SM_6464>>>(
        O, 1024, Wo, 1024, out, 1024);
}